// round 9
// baseline (speedup 1.0000x reference)
#include <cuda_runtime.h>
#include <math.h>

// ---------------------------------------------------------------------------
// Problem constants
// ---------------------------------------------------------------------------
#define DD    1024
#define NTOK  257
#define BATCH 32
#define HEADS 16
#define HDIM  64
#define RR    16
#define NA    129        // even tokens (a side)
#define NB    128        // odd tokens  (b side)
#define NUNM  113        // NA - RR
#define NOUT  241        // NUNM + NB
#define MROWS (BATCH*NTOK)   // 8224
#define MOUT  (BATCH*NOUT)   // 7712

// ---------------------------------------------------------------------------
// Scratch (device globals -- no allocation allowed)
// ---------------------------------------------------------------------------
__device__ float g_h   [MROWS*DD];          // LN1 output (fp32 exact)
__device__ float g_qkv [MROWS*3*DD];        // qkv projections (tf32 accuracy)
__device__ float g_o   [MROWS*DD];          // attention output
__device__ float g_xf  [MROWS*DD];          // x after attention residual
__device__ float g_m   [MROWS*HDIM];        // normalized metric (fp32 path)
__device__ float g_wavgT[DD*HDIM];          // head-averaged Wk, transposed [k][d]
__device__ float g_bavg [HDIM];
__device__ float g_nmax[BATCH*NA];
__device__ int   g_nidx[BATCH*NA];
__device__ int   g_unm [BATCH][NUNM];
__device__ int   g_src [BATCH][RR];
__device__ int   g_dst [BATCH][RR];
__device__ int   g_dcnt[BATCH][NB];
__device__ float g_xm  [MOUT*DD];           // merged x
__device__ float g_h2  [MOUT*DD];           // LN2 output
__device__ float g_t4  [MOUT*4*DD];         // fc+gelu output

// ---------------------------------------------------------------------------
// Helpers
// ---------------------------------------------------------------------------
__device__ __forceinline__ float gelu_exact(float x) {
    return 0.5f * x * (1.0f + erff(x * 0.70710678118654752440f));
}

__device__ __forceinline__ unsigned f2tf(float x) {
    unsigned u;
    asm("cvt.rna.tf32.f32 %0, %1;" : "=r"(u) : "f"(x));
    return u;
}

__device__ __forceinline__ void mma_tf32(float c[4], const unsigned a[4],
                                         const unsigned b[2]) {
    asm volatile(
        "mma.sync.aligned.m16n8k8.row.col.f32.tf32.tf32.f32 "
        "{%0,%1,%2,%3}, {%4,%5,%6,%7}, {%8,%9}, {%0,%1,%2,%3};\n"
        : "+f"(c[0]), "+f"(c[1]), "+f"(c[2]), "+f"(c[3])
        : "r"(a[0]), "r"(a[1]), "r"(a[2]), "r"(a[3]),
          "r"(b[0]), "r"(b[1]));
}

// ---------------------------------------------------------------------------
// LayerNorm: one block per row of 1024, 256 threads (4 floats/thread)
// ---------------------------------------------------------------------------
__global__ __launch_bounds__(256)
void ln_kernel(const float* __restrict__ x, const float* __restrict__ w,
               const float* __restrict__ b, float* __restrict__ y)
{
    int r = blockIdx.x;
    const float4* xr = (const float4*)(x + (size_t)r * DD);
    float4 v = xr[threadIdx.x];
    float s  = v.x + v.y + v.z + v.w;
    float s2 = v.x*v.x + v.y*v.y + v.z*v.z + v.w*v.w;
    #pragma unroll
    for (int off = 16; off; off >>= 1) {
        s  += __shfl_xor_sync(0xffffffffu, s,  off);
        s2 += __shfl_xor_sync(0xffffffffu, s2, off);
    }
    __shared__ float ws[8], ws2[8];
    int wid = threadIdx.x >> 5, lid = threadIdx.x & 31;
    if (lid == 0) { ws[wid] = s; ws2[wid] = s2; }
    __syncthreads();
    __shared__ float smu, srstd;
    if (threadIdx.x == 0) {
        float S = 0, S2 = 0;
        #pragma unroll
        for (int i = 0; i < 8; i++) { S += ws[i]; S2 += ws2[i]; }
        float mu  = S * (1.0f / DD);
        float var = S2 * (1.0f / DD) - mu * mu;
        smu = mu; srstd = rsqrtf(var + 1e-5f);
    }
    __syncthreads();
    float mu = smu, rstd = srstd;
    float4 wv = ((const float4*)w)[threadIdx.x];
    float4 bv = ((const float4*)b)[threadIdx.x];
    float4 o;
    o.x = (v.x - mu) * rstd * wv.x + bv.x;
    o.y = (v.y - mu) * rstd * wv.y + bv.y;
    o.z = (v.z - mu) * rstd * wv.z + bv.z;
    o.w = (v.w - mu) * rstd * wv.w + bv.w;
    ((float4*)(y + (size_t)r * DD))[threadIdx.x] = o;
}

// ---------------------------------------------------------------------------
// TF32 tensor-core GEMM (NT): C[m,n] = sum_k A[m,k]*W[n,k] + bias[n] (+epi)
// BM=BN=128, BK=32, 256 threads, warp tile 64x32 (warps 2x4).
// Smem layout [row][k] with stride 36 floats: conflict-free fragment reads.
// Register-staged gmem prefetch, single smem buffer.
// EPI 0: bias. EPI 1: +Cadd residual. EPI 2: gelu(acc+bias).
// Requires N%128==0, K%32==0; M guarded (rows clamped + epilogue guard).
// ---------------------------------------------------------------------------
#define SAS 36

template<int EPI>
__global__ __launch_bounds__(256, 1)
void gemm_tf32(const float* __restrict__ A, const float* __restrict__ W,
               const float* __restrict__ bias, const float* __restrict__ Cadd,
               float* __restrict__ C, int M, int N, int K)
{
    __shared__ unsigned As[128*SAS];
    __shared__ unsigned Bs[128*SAS];

    int tid = threadIdx.x;
    int bx = blockIdx.x, by = blockIdx.y;
    int rbase = tid >> 3;          // 0..31
    int c4    = tid & 7;           // 0..7  (float4 column group)

    const float* Ap[4];
    const float* Wp[4];
    #pragma unroll
    for (int i = 0; i < 4; i++) {
        int ar = by*128 + rbase + 32*i;
        if (ar >= M) ar = M - 1;                // clamp (epilogue guards)
        Ap[i] = A + (size_t)ar * K + c4*4;
        Wp[i] = W + (size_t)(bx*128 + rbase + 32*i) * K + c4*4;
    }

    float4 areg[4], breg[4];
    #pragma unroll
    for (int i = 0; i < 4; i++) {
        areg[i] = *(const float4*)(Ap[i]);
        breg[i] = *(const float4*)(Wp[i]);
    }

    float acc[4][4][4];
    #pragma unroll
    for (int mt = 0; mt < 4; mt++)
        #pragma unroll
        for (int nt = 0; nt < 4; nt++)
            #pragma unroll
            for (int q = 0; q < 4; q++) acc[mt][nt][q] = 0.0f;

    int w = tid >> 5, l = tid & 31;
    int wm = w >> 2, wn = w & 3;          // 2 x 4 warp grid
    int mrow = l >> 2;                    // 0..7
    int kc   = l & 3;                     // 0..3

    for (int kc0 = 0; kc0 < K; kc0 += 32) {
        // stage regs -> smem (with tf32 rounding)
        #pragma unroll
        for (int i = 0; i < 4; i++) {
            int so = (rbase + 32*i) * SAS + c4*4;
            As[so+0] = f2tf(areg[i].x); As[so+1] = f2tf(areg[i].y);
            As[so+2] = f2tf(areg[i].z); As[so+3] = f2tf(areg[i].w);
            Bs[so+0] = f2tf(breg[i].x); Bs[so+1] = f2tf(breg[i].y);
            Bs[so+2] = f2tf(breg[i].z); Bs[so+3] = f2tf(breg[i].w);
        }
        __syncthreads();

        bool more = (kc0 + 32) < K;
        if (more) {
            #pragma unroll
            for (int i = 0; i < 4; i++) {
                areg[i] = *(const float4*)(Ap[i] + kc0 + 32);
                breg[i] = *(const float4*)(Wp[i] + kc0 + 32);
            }
        }

        #pragma unroll
        for (int kk = 0; kk < 4; kk++) {
            unsigned af[4][4], bf[4][2];
            #pragma unroll
            for (int mt = 0; mt < 4; mt++) {
                int base = (wm*64 + mt*16 + mrow) * SAS + kk*8 + kc;
                af[mt][0] = As[base];
                af[mt][1] = As[base + 8*SAS];
                af[mt][2] = As[base + 4];
                af[mt][3] = As[base + 8*SAS + 4];
            }
            #pragma unroll
            for (int nt = 0; nt < 4; nt++) {
                int base = (wn*32 + nt*8 + mrow) * SAS + kk*8 + kc;
                bf[nt][0] = Bs[base];
                bf[nt][1] = Bs[base + 4];
            }
            #pragma unroll
            for (int mt = 0; mt < 4; mt++)
                #pragma unroll
                for (int nt = 0; nt < 4; nt++)
                    mma_tf32(acc[mt][nt], af[mt], bf[nt]);
        }
        if (more) __syncthreads();
    }

    // epilogue
    int gr0 = by*128 + wm*64;
    int gc0 = bx*128 + wn*32;
    #pragma unroll
    for (int mt = 0; mt < 4; mt++) {
        #pragma unroll
        for (int nt = 0; nt < 4; nt++) {
            int col = gc0 + nt*8 + kc*2;
            float2 bv = *(const float2*)(bias + col);
            #pragma unroll
            for (int half = 0; half < 2; half++) {
                int row = gr0 + mt*16 + mrow + half*8;
                if (row >= M) continue;
                float r0 = acc[mt][nt][half*2+0] + bv.x;
                float r1 = acc[mt][nt][half*2+1] + bv.y;
                if constexpr (EPI == 1) {
                    float2 cv = *(const float2*)(Cadd + (size_t)row*N + col);
                    r0 += cv.x; r1 += cv.y;
                }
                if constexpr (EPI == 2) {
                    r0 = gelu_exact(r0); r1 = gelu_exact(r1);
                }
                float2 ov = {r0, r1};
                *(float2*)(C + (size_t)row*N + col) = ov;
            }
        }
    }
}

// ---------------------------------------------------------------------------
// Fused attention: one block per (b,h). K,V resident in smem (stride 65),
// per-warp softmax over 257 keys.
// ---------------------------------------------------------------------------
#define KST 65
#define PRST 260
__global__ __launch_bounds__(256)
void attn_kernel(const float* __restrict__ qkv, float* __restrict__ o)
{
    extern __shared__ float sm[];
    float* Ks = sm;                       // 257*65
    float* Vs = sm + NTOK*KST;            // 257*65
    float* Pr = Vs + NTOK*KST;            // 8*260
    float* Qb = Pr + 8*PRST;              // 8*64

    int bh = blockIdx.x;
    int b = bh >> 4, hh = bh & 15;
    const float* base = qkv + (size_t)b * NTOK * (3*DD);

    for (int idx = threadIdx.x; idx < NTOK*HDIM; idx += blockDim.x) {
        int j = idx >> 6, d = idx & 63;
        Ks[j*KST + d] = base[(size_t)j*(3*DD) + DD   + hh*HDIM + d];
        Vs[j*KST + d] = base[(size_t)j*(3*DD) + 2*DD + hh*HDIM + d];
    }
    __syncthreads();

    int w = threadIdx.x >> 5, l = threadIdx.x & 31;
    float* pr = Pr + w * PRST;
    float* qb = Qb + w * HDIM;

    for (int n = w; n < NTOK; n += 8) {
        const float* qrow = base + (size_t)n*(3*DD) + hh*HDIM;
        qb[l]      = qrow[l];
        qb[l + 32] = qrow[l + 32];
        __syncwarp();
        float mx = -INFINITY;
        for (int j = l; j < NTOK; j += 32) {
            float s = 0.0f;
            #pragma unroll
            for (int d = 0; d < HDIM; d++) s += qb[d] * Ks[j*KST + d];
            s *= 0.125f;
            pr[j] = s;
            mx = fmaxf(mx, s);
        }
        #pragma unroll
        for (int off = 16; off; off >>= 1)
            mx = fmaxf(mx, __shfl_xor_sync(0xffffffffu, mx, off));
        float sum = 0.0f;
        for (int j = l; j < NTOK; j += 32) {
            float e = expf(pr[j] - mx);
            pr[j] = e;
            sum += e;
        }
        #pragma unroll
        for (int off = 16; off; off >>= 1)
            sum += __shfl_xor_sync(0xffffffffu, sum, off);
        float inv = 1.0f / sum;
        __syncwarp();
        float o0 = 0.0f, o1 = 0.0f;
        for (int j = 0; j < NTOK; j++) {
            float p = pr[j];
            o0 += p * Vs[j*KST + l];
            o1 += p * Vs[j*KST + l + 32];
        }
        float* orow = o + ((size_t)b*NTOK + n) * DD + hh*HDIM;
        orow[l]      = o0 * inv;
        orow[l + 32] = o1 * inv;
        __syncwarp();
    }
}

// ---------------------------------------------------------------------------
// Head-averaged k-weights (fp32 exact metric path):
// wavgT[c*64+d] = mean_h in_proj_w[D + h*64 + d][c]; bavg likewise.
// ---------------------------------------------------------------------------
__global__ __launch_bounds__(256)
void wavg_kernel(const float* __restrict__ Wqkv, const float* __restrict__ bqkv,
                 float* __restrict__ wavgT, float* __restrict__ bavg)
{
    int d = blockIdx.x;                   // 0..63
    for (int c = threadIdx.x; c < DD; c += 256) {
        float s = 0.0f;
        #pragma unroll
        for (int h = 0; h < HEADS; h++)
            s += Wqkv[(size_t)(DD + h*HDIM + d) * DD + c];
        wavgT[c*HDIM + d] = s * (1.0f / HEADS);
    }
    if (threadIdx.x == 0) {
        float s = 0.0f;
        #pragma unroll
        for (int h = 0; h < HEADS; h++) s += bqkv[DD + h*HDIM + d];
        bavg[d] = s * (1.0f / HEADS);
    }
}

// ---------------------------------------------------------------------------
// metric row: m[row][d] = normalize_d( dot(h_row, wavgT[:,d]) + bavg[d] )
// Block per row, 256 threads: thread (seg = tid>>6, d = tid&63).
// ---------------------------------------------------------------------------
__global__ __launch_bounds__(256)
void metricrow_kernel(const float* __restrict__ h,
                      const float* __restrict__ wavgT,
                      const float* __restrict__ bavg,
                      float* __restrict__ m)
{
    int row = blockIdx.x;
    __shared__ float hs[DD];
    ((float4*)hs)[threadIdx.x] =
        ((const float4*)(h + (size_t)row * DD))[threadIdx.x];
    __syncthreads();

    int d = threadIdx.x & 63, seg = threadIdx.x >> 6;
    const float* wp = wavgT + (size_t)seg * 256 * HDIM + d;
    const float* hp = hs + seg * 256;
    float acc = 0.0f;
    #pragma unroll 8
    for (int k = 0; k < 256; k++) acc += hp[k] * wp[k*HDIM];

    __shared__ float red[256];
    red[threadIdx.x] = acc;
    __syncthreads();

    float v = 0.0f;
    if (threadIdx.x < 64)
        v = red[d] + red[64+d] + red[128+d] + red[192+d] + bavg[d];
    float sq = v * v;
    #pragma unroll
    for (int off = 16; off; off >>= 1)
        sq += __shfl_xor_sync(0xffffffffu, sq, off);
    __shared__ float s2w[8];
    if ((threadIdx.x & 31) == 0) s2w[threadIdx.x >> 5] = sq;
    __syncthreads();
    if (threadIdx.x < 64) {
        float tot = s2w[0] + s2w[1];
        m[(size_t)row * HDIM + d] = v * rsqrtf(tot);
    }
}

// ---------------------------------------------------------------------------
// node scores: block (i,b) computes max_j dot(a_i, bm_j) and argmax (first
// max wins). Row i==0 forced to -inf.
// ---------------------------------------------------------------------------
__global__ __launch_bounds__(128)
void nodescore_kernel(const float* __restrict__ m,
                      float* __restrict__ nmax, int* __restrict__ nidx)
{
    int i = blockIdx.x, b = blockIdx.y;
    if (i == 0) {
        if (threadIdx.x == 0) { nmax[b*NA] = -INFINITY; nidx[b*NA] = 0; }
        return;
    }
    __shared__ float av[HDIM];
    if (threadIdx.x < HDIM)
        av[threadIdx.x] = m[((size_t)b*NTOK + 2*i) * HDIM + threadIdx.x];
    __syncthreads();
    int j = threadIdx.x;
    const float* bm = m + ((size_t)b*NTOK + 2*j + 1) * HDIM;
    float s = 0.0f;
    #pragma unroll
    for (int d = 0; d < HDIM; d++) s += av[d] * bm[d];
    __shared__ float sv[128];
    __shared__ int   si[128];
    sv[j] = s; si[j] = j;
    __syncthreads();
    #pragma unroll
    for (int st = 64; st; st >>= 1) {
        if (threadIdx.x < st) {
            float o = sv[threadIdx.x + st]; int oi = si[threadIdx.x + st];
            if (o > sv[threadIdx.x] ||
                (o == sv[threadIdx.x] && oi < si[threadIdx.x])) {
                sv[threadIdx.x] = o; si[threadIdx.x] = oi;
            }
        }
        __syncthreads();
    }
    if (threadIdx.x == 0) { nmax[b*NA + i] = sv[0]; nidx[b*NA + i] = si[0]; }
}

// ---------------------------------------------------------------------------
// Stable descending argsort via ranks; build unm/src/dst/dcnt per batch.
// ---------------------------------------------------------------------------
__global__ __launch_bounds__(160)
void topo_kernel(const float* __restrict__ nmax, const int* __restrict__ nidx)
{
    int b = blockIdx.x;
    __shared__ float nm[NA];
    __shared__ int   rk[NA];
    int t = threadIdx.x;
    if (t < NA) nm[t] = nmax[b*NA + t];
    __syncthreads();
    if (t < NA) {
        float mi = nm[t];
        int r = 0;
        for (int j = 0; j < NA; j++) {
            float mj = nm[j];
            r += (mj > mi) || (mj == mi && j < t);
        }
        rk[t] = r;
        if (r < RR) {
            g_src[b][r] = t;
            g_dst[b][r] = nidx[b*NA + t];
        }
    }
    __syncthreads();
    if (t == 0) {
        int pos = 0;
        for (int i = 0; i < NA; i++)
            if (rk[i] >= RR) g_unm[b][pos++] = i;
    }
    if (t < NB) {
        int c = 0;
        for (int k = 0; k < RR; k++) c += (g_dst[b][k] == t);
        g_dcnt[b][t] = c;
    }
}

// ---------------------------------------------------------------------------
// ToME merge: out token t<113 = s[unm[t]]; else d[j] + mapped src, / size.
// ---------------------------------------------------------------------------
__global__ __launch_bounds__(256)
void merge_kernel(const float* __restrict__ xf, float* __restrict__ xm)
{
    int t = blockIdx.x % NOUT;
    int b = blockIdx.x / NOUT;
    __shared__ int ssrc[RR], sdst[RR];
    if (threadIdx.x < RR) {
        ssrc[threadIdx.x] = g_src[b][threadIdx.x];
        sdst[threadIdx.x] = g_dst[b][threadIdx.x];
    }
    __syncthreads();
    size_t brow = (size_t)b * NTOK;
    float4* out = (float4*)(xm + ((size_t)b * NOUT + t) * DD);
    int d = threadIdx.x;
    if (t < NUNM) {
        int u = g_unm[b][t];
        const float4* src = (const float4*)(xf + (brow + 2*u) * DD);
        out[d] = src[d];
    } else {
        int j = t - NUNM;
        const float4* dsrc = (const float4*)(xf + (brow + 2*j + 1) * DD);
        float4 v = dsrc[d];
        int cnt = g_dcnt[b][j];
        if (cnt) {
            #pragma unroll
            for (int k = 0; k < RR; k++) {
                if (sdst[k] == j) {
                    const float4* s2 =
                        (const float4*)(xf + (brow + 2*ssrc[k]) * DD);
                    float4 a = s2[d];
                    v.x += a.x; v.y += a.y; v.z += a.z; v.w += a.w;
                }
            }
            float inv = 1.0f / (float)(1 + cnt);
            v.x *= inv; v.y *= inv; v.z *= inv; v.w *= inv;
        }
        out[d] = v;
    }
}

// ---------------------------------------------------------------------------
// kernel_launch
// ---------------------------------------------------------------------------
extern "C" void kernel_launch(void* const* d_in, const int* in_sizes, int n_in,
                              void* d_out, int out_size)
{
    const float* q_x       = (const float*)d_in[0];
    const float* ln1_w     = (const float*)d_in[1];
    const float* ln1_b     = (const float*)d_in[2];
    const float* in_proj_w = (const float*)d_in[3];
    const float* in_proj_b = (const float*)d_in[4];
    const float* out_w     = (const float*)d_in[5];
    const float* out_b     = (const float*)d_in[6];
    const float* ln2_w     = (const float*)d_in[7];
    const float* ln2_b     = (const float*)d_in[8];
    const float* fc_w      = (const float*)d_in[9];
    const float* fc_b      = (const float*)d_in[10];
    const float* proj_w    = (const float*)d_in[11];
    const float* proj_b    = (const float*)d_in[12];
    float* outp = (float*)d_out;

    float *p_h, *p_qkv, *p_o, *p_xf, *p_m, *p_nmax, *p_xm, *p_h2, *p_t4;
    float *p_wavgT, *p_bavg;
    int *p_nidx;
    cudaGetSymbolAddress((void**)&p_h,     g_h);
    cudaGetSymbolAddress((void**)&p_qkv,   g_qkv);
    cudaGetSymbolAddress((void**)&p_o,     g_o);
    cudaGetSymbolAddress((void**)&p_xf,    g_xf);
    cudaGetSymbolAddress((void**)&p_m,     g_m);
    cudaGetSymbolAddress((void**)&p_wavgT, g_wavgT);
    cudaGetSymbolAddress((void**)&p_bavg,  g_bavg);
    cudaGetSymbolAddress((void**)&p_nmax,  g_nmax);
    cudaGetSymbolAddress((void**)&p_nidx,  g_nidx);
    cudaGetSymbolAddress((void**)&p_xm,    g_xm);
    cudaGetSymbolAddress((void**)&p_h2,    g_h2);
    cudaGetSymbolAddress((void**)&p_t4,    g_t4);

    static const int ATT_SMEM = (NTOK*KST*2 + 8*PRST + 8*HDIM) * 4;
    cudaFuncSetAttribute(attn_kernel,
                         cudaFuncAttributeMaxDynamicSharedMemorySize, ATT_SMEM);

    // 0. head-averaged k weights (exact metric path)
    wavg_kernel<<<HDIM, 256>>>(in_proj_w, in_proj_b, p_wavgT, p_bavg);

    // 1. LN1
    ln_kernel<<<MROWS, 256>>>(q_x, ln1_w, ln1_b, p_h);

    // 2. qkv = h @ in_proj_w^T + b  (TF32 tensor cores)
    gemm_tf32<0><<<dim3(3072/128, (MROWS+127)/128), 256>>>(
        p_h, in_proj_w, in_proj_b, nullptr, p_qkv, MROWS, 3072, 1024);

    // 3. metric (fp32 exact) + normalize
    metricrow_kernel<<<MROWS, 256>>>(p_h, p_wavgT, p_bavg, p_m);

    // 4. attention -> o
    attn_kernel<<<BATCH*HEADS, 256, ATT_SMEM>>>(p_qkv, p_o);

    // 5. x = q_x + o @ out_w^T + out_b
    gemm_tf32<1><<<dim3(1024/128, (MROWS+127)/128), 256>>>(
        p_o, out_w, out_b, q_x, p_xf, MROWS, 1024, 1024);

    // 6. node scores
    nodescore_kernel<<<dim3(NA, BATCH), 128>>>(p_m, p_nmax, p_nidx);

    // 7. stable ranks / merge bookkeeping
    topo_kernel<<<BATCH, 160>>>(p_nmax, p_nidx);

    // 8. merge tokens 257 -> 241
    merge_kernel<<<BATCH*NOUT, 256>>>(p_xf, p_xm);

    // 9. LN2
    ln_kernel<<<MOUT, 256>>>(p_xm, ln2_w, ln2_b, p_h2);

    // 10. t = gelu(h2 @ fc_w^T + fc_b)
    gemm_tf32<2><<<dim3(4096/128, (MOUT+127)/128), 256>>>(
        p_h2, fc_w, fc_b, nullptr, p_t4, MOUT, 4096, 1024);

    // 11. out = x + t @ proj_w^T + proj_b
    gemm_tf32<1><<<dim3(1024/128, (MOUT+127)/128), 256>>>(
        p_t4, proj_w, proj_b, p_xm, outp, MOUT, 1024, 4096);
}

// round 10
// speedup vs baseline: 1.0015x; 1.0015x over previous
#include <cuda_runtime.h>
#include <math.h>

// ---------------------------------------------------------------------------
// Problem constants
// ---------------------------------------------------------------------------
#define DD    1024
#define NTOK  257
#define BATCH 32
#define HEADS 16
#define HDIM  64
#define RR    16
#define NA    129        // even tokens (a side)
#define NB    128        // odd tokens  (b side)
#define NUNM  113        // NA - RR
#define NOUT  241        // NUNM + NB
#define MROWS (BATCH*NTOK)   // 8224
#define MOUT  (BATCH*NOUT)   // 7712

// ---------------------------------------------------------------------------
// Scratch (device globals -- no allocation allowed)
// ---------------------------------------------------------------------------
__device__ float g_h   [MROWS*DD];          // LN1 output (fp32 exact)
__device__ float g_qkv [MROWS*3*DD];        // qkv projections (tf32 accuracy)
__device__ float g_o   [MROWS*DD];          // attention output
__device__ float g_xf  [MROWS*DD];          // x after attention residual
__device__ float g_m   [MROWS*HDIM];        // normalized metric (fp32 path)
__device__ float g_wavgT[DD*HDIM];          // head-averaged Wk, transposed [k][d]
__device__ float g_bavg [HDIM];
__device__ float g_nmax[BATCH*NA];
__device__ int   g_nidx[BATCH*NA];
__device__ int   g_unm [BATCH][NUNM];
__device__ int   g_src [BATCH][RR];
__device__ int   g_dst [BATCH][RR];
__device__ int   g_dcnt[BATCH][NB];
__device__ float g_xm  [MOUT*DD];           // merged x
__device__ float g_h2  [MOUT*DD];           // LN2 output
__device__ float g_t4  [MOUT*4*DD];         // fc+gelu output

// ---------------------------------------------------------------------------
// Helpers
// ---------------------------------------------------------------------------
__device__ __forceinline__ float gelu_exact(float x) {
    return 0.5f * x * (1.0f + erff(x * 0.70710678118654752440f));
}

__device__ __forceinline__ unsigned f2tf(float x) {
    unsigned u;
    asm("cvt.rna.tf32.f32 %0, %1;" : "=r"(u) : "f"(x));
    return u;
}

__device__ __forceinline__ void mma_tf32(float c[4], const unsigned a[4],
                                         const unsigned b[2]) {
    asm volatile(
        "mma.sync.aligned.m16n8k8.row.col.f32.tf32.tf32.f32 "
        "{%0,%1,%2,%3}, {%4,%5,%6,%7}, {%8,%9}, {%0,%1,%2,%3};\n"
        : "+f"(c[0]), "+f"(c[1]), "+f"(c[2]), "+f"(c[3])
        : "r"(a[0]), "r"(a[1]), "r"(a[2]), "r"(a[3]),
          "r"(b[0]), "r"(b[1]));
}

// ---------------------------------------------------------------------------
// LayerNorm: one block per row of 1024, 256 threads (4 floats/thread)
// ---------------------------------------------------------------------------
__global__ __launch_bounds__(256)
void ln_kernel(const float* __restrict__ x, const float* __restrict__ w,
               const float* __restrict__ b, float* __restrict__ y)
{
    int r = blockIdx.x;
    const float4* xr = (const float4*)(x + (size_t)r * DD);
    float4 v = xr[threadIdx.x];
    float s  = v.x + v.y + v.z + v.w;
    float s2 = v.x*v.x + v.y*v.y + v.z*v.z + v.w*v.w;
    #pragma unroll
    for (int off = 16; off; off >>= 1) {
        s  += __shfl_xor_sync(0xffffffffu, s,  off);
        s2 += __shfl_xor_sync(0xffffffffu, s2, off);
    }
    __shared__ float ws[8], ws2[8];
    int wid = threadIdx.x >> 5, lid = threadIdx.x & 31;
    if (lid == 0) { ws[wid] = s; ws2[wid] = s2; }
    __syncthreads();
    __shared__ float smu, srstd;
    if (threadIdx.x == 0) {
        float S = 0, S2 = 0;
        #pragma unroll
        for (int i = 0; i < 8; i++) { S += ws[i]; S2 += ws2[i]; }
        float mu  = S * (1.0f / DD);
        float var = S2 * (1.0f / DD) - mu * mu;
        smu = mu; srstd = rsqrtf(var + 1e-5f);
    }
    __syncthreads();
    float mu = smu, rstd = srstd;
    float4 wv = ((const float4*)w)[threadIdx.x];
    float4 bv = ((const float4*)b)[threadIdx.x];
    float4 o;
    o.x = (v.x - mu) * rstd * wv.x + bv.x;
    o.y = (v.y - mu) * rstd * wv.y + bv.y;
    o.z = (v.z - mu) * rstd * wv.z + bv.z;
    o.w = (v.w - mu) * rstd * wv.w + bv.w;
    ((float4*)(y + (size_t)r * DD))[threadIdx.x] = o;
}

// ---------------------------------------------------------------------------
// TF32 tensor-core GEMM (NT): C[m,n] = sum_k A[m,k]*W[n,k] + bias[n] (+epi)
// BM=BN=128, BK=32, 256 threads, warp tile 64x32 (warps 2x4).
// Smem layout [row][k] with stride 36 floats: conflict-free fragment reads.
// Register-staged gmem prefetch, single smem buffer.
// EPI 0: bias. EPI 1: +Cadd residual. EPI 2: gelu(acc+bias).
// Requires N%128==0, K%32==0; M guarded (rows clamped + epilogue guard).
// ---------------------------------------------------------------------------
#define SAS 36

template<int EPI>
__global__ __launch_bounds__(256, 1)
void gemm_tf32(const float* __restrict__ A, const float* __restrict__ W,
               const float* __restrict__ bias, const float* __restrict__ Cadd,
               float* __restrict__ C, int M, int N, int K)
{
    __shared__ unsigned As[128*SAS];
    __shared__ unsigned Bs[128*SAS];

    int tid = threadIdx.x;
    int bx = blockIdx.x, by = blockIdx.y;
    int rbase = tid >> 3;          // 0..31
    int c4    = tid & 7;           // 0..7  (float4 column group)

    const float* Ap[4];
    const float* Wp[4];
    #pragma unroll
    for (int i = 0; i < 4; i++) {
        int ar = by*128 + rbase + 32*i;
        if (ar >= M) ar = M - 1;                // clamp (epilogue guards)
        Ap[i] = A + (size_t)ar * K + c4*4;
        Wp[i] = W + (size_t)(bx*128 + rbase + 32*i) * K + c4*4;
    }

    float4 areg[4], breg[4];
    #pragma unroll
    for (int i = 0; i < 4; i++) {
        areg[i] = *(const float4*)(Ap[i]);
        breg[i] = *(const float4*)(Wp[i]);
    }

    float acc[4][4][4];
    #pragma unroll
    for (int mt = 0; mt < 4; mt++)
        #pragma unroll
        for (int nt = 0; nt < 4; nt++)
            #pragma unroll
            for (int q = 0; q < 4; q++) acc[mt][nt][q] = 0.0f;

    int w = tid >> 5, l = tid & 31;
    int wm = w >> 2, wn = w & 3;          // 2 x 4 warp grid
    int mrow = l >> 2;                    // 0..7
    int kc   = l & 3;                     // 0..3

    for (int kc0 = 0; kc0 < K; kc0 += 32) {
        // stage regs -> smem (with tf32 rounding)
        #pragma unroll
        for (int i = 0; i < 4; i++) {
            int so = (rbase + 32*i) * SAS + c4*4;
            As[so+0] = f2tf(areg[i].x); As[so+1] = f2tf(areg[i].y);
            As[so+2] = f2tf(areg[i].z); As[so+3] = f2tf(areg[i].w);
            Bs[so+0] = f2tf(breg[i].x); Bs[so+1] = f2tf(breg[i].y);
            Bs[so+2] = f2tf(breg[i].z); Bs[so+3] = f2tf(breg[i].w);
        }
        __syncthreads();

        bool more = (kc0 + 32) < K;
        if (more) {
            #pragma unroll
            for (int i = 0; i < 4; i++) {
                areg[i] = *(const float4*)(Ap[i] + kc0 + 32);
                breg[i] = *(const float4*)(Wp[i] + kc0 + 32);
            }
        }

        #pragma unroll
        for (int kk = 0; kk < 4; kk++) {
            unsigned af[4][4], bf[4][2];
            #pragma unroll
            for (int mt = 0; mt < 4; mt++) {
                int base = (wm*64 + mt*16 + mrow) * SAS + kk*8 + kc;
                af[mt][0] = As[base];
                af[mt][1] = As[base + 8*SAS];
                af[mt][2] = As[base + 4];
                af[mt][3] = As[base + 8*SAS + 4];
            }
            #pragma unroll
            for (int nt = 0; nt < 4; nt++) {
                int base = (wn*32 + nt*8 + mrow) * SAS + kk*8 + kc;
                bf[nt][0] = Bs[base];
                bf[nt][1] = Bs[base + 4];
            }
            #pragma unroll
            for (int mt = 0; mt < 4; mt++)
                #pragma unroll
                for (int nt = 0; nt < 4; nt++)
                    mma_tf32(acc[mt][nt], af[mt], bf[nt]);
        }
        if (more) __syncthreads();
    }

    // epilogue
    int gr0 = by*128 + wm*64;
    int gc0 = bx*128 + wn*32;
    #pragma unroll
    for (int mt = 0; mt < 4; mt++) {
        #pragma unroll
        for (int nt = 0; nt < 4; nt++) {
            int col = gc0 + nt*8 + kc*2;
            float2 bv = *(const float2*)(bias + col);
            #pragma unroll
            for (int half = 0; half < 2; half++) {
                int row = gr0 + mt*16 + mrow + half*8;
                if (row >= M) continue;
                float r0 = acc[mt][nt][half*2+0] + bv.x;
                float r1 = acc[mt][nt][half*2+1] + bv.y;
                if constexpr (EPI == 1) {
                    float2 cv = *(const float2*)(Cadd + (size_t)row*N + col);
                    r0 += cv.x; r1 += cv.y;
                }
                if constexpr (EPI == 2) {
                    r0 = gelu_exact(r0); r1 = gelu_exact(r1);
                }
                float2 ov = {r0, r1};
                *(float2*)(C + (size_t)row*N + col) = ov;
            }
        }
    }
}

// ---------------------------------------------------------------------------
// Fused attention: one block per (b,h). K,V resident in smem (stride 65),
// per-warp softmax over 257 keys.
// ---------------------------------------------------------------------------
#define KST 65
#define PRST 260
__global__ __launch_bounds__(256)
void attn_kernel(const float* __restrict__ qkv, float* __restrict__ o)
{
    extern __shared__ float sm[];
    float* Ks = sm;                       // 257*65
    float* Vs = sm + NTOK*KST;            // 257*65
    float* Pr = Vs + NTOK*KST;            // 8*260
    float* Qb = Pr + 8*PRST;              // 8*64

    int bh = blockIdx.x;
    int b = bh >> 4, hh = bh & 15;
    const float* base = qkv + (size_t)b * NTOK * (3*DD);

    for (int idx = threadIdx.x; idx < NTOK*HDIM; idx += blockDim.x) {
        int j = idx >> 6, d = idx & 63;
        Ks[j*KST + d] = base[(size_t)j*(3*DD) + DD   + hh*HDIM + d];
        Vs[j*KST + d] = base[(size_t)j*(3*DD) + 2*DD + hh*HDIM + d];
    }
    __syncthreads();

    int w = threadIdx.x >> 5, l = threadIdx.x & 31;
    float* pr = Pr + w * PRST;
    float* qb = Qb + w * HDIM;

    for (int n = w; n < NTOK; n += 8) {
        const float* qrow = base + (size_t)n*(3*DD) + hh*HDIM;
        qb[l]      = qrow[l];
        qb[l + 32] = qrow[l + 32];
        __syncwarp();
        float mx = -INFINITY;
        for (int j = l; j < NTOK; j += 32) {
            float s = 0.0f;
            #pragma unroll
            for (int d = 0; d < HDIM; d++) s += qb[d] * Ks[j*KST + d];
            s *= 0.125f;
            pr[j] = s;
            mx = fmaxf(mx, s);
        }
        #pragma unroll
        for (int off = 16; off; off >>= 1)
            mx = fmaxf(mx, __shfl_xor_sync(0xffffffffu, mx, off));
        float sum = 0.0f;
        for (int j = l; j < NTOK; j += 32) {
            float e = expf(pr[j] - mx);
            pr[j] = e;
            sum += e;
        }
        #pragma unroll
        for (int off = 16; off; off >>= 1)
            sum += __shfl_xor_sync(0xffffffffu, sum, off);
        float inv = 1.0f / sum;
        __syncwarp();
        float o0 = 0.0f, o1 = 0.0f;
        for (int j = 0; j < NTOK; j++) {
            float p = pr[j];
            o0 += p * Vs[j*KST + l];
            o1 += p * Vs[j*KST + l + 32];
        }
        float* orow = o + ((size_t)b*NTOK + n) * DD + hh*HDIM;
        orow[l]      = o0 * inv;
        orow[l + 32] = o1 * inv;
        __syncwarp();
    }
}

// ---------------------------------------------------------------------------
// Head-averaged k-weights (fp32 exact metric path):
// wavgT[c*64+d] = mean_h in_proj_w[D + h*64 + d][c]; bavg likewise.
// ---------------------------------------------------------------------------
__global__ __launch_bounds__(256)
void wavg_kernel(const float* __restrict__ Wqkv, const float* __restrict__ bqkv,
                 float* __restrict__ wavgT, float* __restrict__ bavg)
{
    int d = blockIdx.x;                   // 0..63
    for (int c = threadIdx.x; c < DD; c += 256) {
        float s = 0.0f;
        #pragma unroll
        for (int h = 0; h < HEADS; h++)
            s += Wqkv[(size_t)(DD + h*HDIM + d) * DD + c];
        wavgT[c*HDIM + d] = s * (1.0f / HEADS);
    }
    if (threadIdx.x == 0) {
        float s = 0.0f;
        #pragma unroll
        for (int h = 0; h < HEADS; h++) s += bqkv[DD + h*HDIM + d];
        bavg[d] = s * (1.0f / HEADS);
    }
}

// ---------------------------------------------------------------------------
// metric row: m[row][d] = normalize_d( dot(h_row, wavgT[:,d]) + bavg[d] )
// Block per row, 256 threads: thread (seg = tid>>6, d = tid&63).
// ---------------------------------------------------------------------------
__global__ __launch_bounds__(256)
void metricrow_kernel(const float* __restrict__ h,
                      const float* __restrict__ wavgT,
                      const float* __restrict__ bavg,
                      float* __restrict__ m)
{
    int row = blockIdx.x;
    __shared__ float hs[DD];
    ((float4*)hs)[threadIdx.x] =
        ((const float4*)(h + (size_t)row * DD))[threadIdx.x];
    __syncthreads();

    int d = threadIdx.x & 63, seg = threadIdx.x >> 6;
    const float* wp = wavgT + (size_t)seg * 256 * HDIM + d;
    const float* hp = hs + seg * 256;
    float acc = 0.0f;
    #pragma unroll 8
    for (int k = 0; k < 256; k++) acc += hp[k] * wp[k*HDIM];

    __shared__ float red[256];
    red[threadIdx.x] = acc;
    __syncthreads();

    float v = 0.0f;
    if (threadIdx.x < 64)
        v = red[d] + red[64+d] + red[128+d] + red[192+d] + bavg[d];
    float sq = v * v;
    #pragma unroll
    for (int off = 16; off; off >>= 1)
        sq += __shfl_xor_sync(0xffffffffu, sq, off);
    __shared__ float s2w[8];
    if ((threadIdx.x & 31) == 0) s2w[threadIdx.x >> 5] = sq;
    __syncthreads();
    if (threadIdx.x < 64) {
        float tot = s2w[0] + s2w[1];
        m[(size_t)row * HDIM + d] = v * rsqrtf(tot);
    }
}

// ---------------------------------------------------------------------------
// node scores: block (i,b) computes max_j dot(a_i, bm_j) and argmax (first
// max wins). Row i==0 forced to -inf.
// ---------------------------------------------------------------------------
__global__ __launch_bounds__(128)
void nodescore_kernel(const float* __restrict__ m,
                      float* __restrict__ nmax, int* __restrict__ nidx)
{
    int i = blockIdx.x, b = blockIdx.y;
    if (i == 0) {
        if (threadIdx.x == 0) { nmax[b*NA] = -INFINITY; nidx[b*NA] = 0; }
        return;
    }
    __shared__ float av[HDIM];
    if (threadIdx.x < HDIM)
        av[threadIdx.x] = m[((size_t)b*NTOK + 2*i) * HDIM + threadIdx.x];
    __syncthreads();
    int j = threadIdx.x;
    const float* bm = m + ((size_t)b*NTOK + 2*j + 1) * HDIM;
    float s = 0.0f;
    #pragma unroll
    for (int d = 0; d < HDIM; d++) s += av[d] * bm[d];
    __shared__ float sv[128];
    __shared__ int   si[128];
    sv[j] = s; si[j] = j;
    __syncthreads();
    #pragma unroll
    for (int st = 64; st; st >>= 1) {
        if (threadIdx.x < st) {
            float o = sv[threadIdx.x + st]; int oi = si[threadIdx.x + st];
            if (o > sv[threadIdx.x] ||
                (o == sv[threadIdx.x] && oi < si[threadIdx.x])) {
                sv[threadIdx.x] = o; si[threadIdx.x] = oi;
            }
        }
        __syncthreads();
    }
    if (threadIdx.x == 0) { nmax[b*NA + i] = sv[0]; nidx[b*NA + i] = si[0]; }
}

// ---------------------------------------------------------------------------
// Stable descending argsort via ranks; build unm/src/dst/dcnt per batch.
// ---------------------------------------------------------------------------
__global__ __launch_bounds__(160)
void topo_kernel(const float* __restrict__ nmax, const int* __restrict__ nidx)
{
    int b = blockIdx.x;
    __shared__ float nm[NA];
    __shared__ int   rk[NA];
    int t = threadIdx.x;
    if (t < NA) nm[t] = nmax[b*NA + t];
    __syncthreads();
    if (t < NA) {
        float mi = nm[t];
        int r = 0;
        for (int j = 0; j < NA; j++) {
            float mj = nm[j];
            r += (mj > mi) || (mj == mi && j < t);
        }
        rk[t] = r;
        if (r < RR) {
            g_src[b][r] = t;
            g_dst[b][r] = nidx[b*NA + t];
        }
    }
    __syncthreads();
    if (t == 0) {
        int pos = 0;
        for (int i = 0; i < NA; i++)
            if (rk[i] >= RR) g_unm[b][pos++] = i;
    }
    if (t < NB) {
        int c = 0;
        for (int k = 0; k < RR; k++) c += (g_dst[b][k] == t);
        g_dcnt[b][t] = c;
    }
}

// ---------------------------------------------------------------------------
// ToME merge: out token t<113 = s[unm[t]]; else d[j] + mapped src, / size.
// ---------------------------------------------------------------------------
__global__ __launch_bounds__(256)
void merge_kernel(const float* __restrict__ xf, float* __restrict__ xm)
{
    int t = blockIdx.x % NOUT;
    int b = blockIdx.x / NOUT;
    __shared__ int ssrc[RR], sdst[RR];
    if (threadIdx.x < RR) {
        ssrc[threadIdx.x] = g_src[b][threadIdx.x];
        sdst[threadIdx.x] = g_dst[b][threadIdx.x];
    }
    __syncthreads();
    size_t brow = (size_t)b * NTOK;
    float4* out = (float4*)(xm + ((size_t)b * NOUT + t) * DD);
    int d = threadIdx.x;
    if (t < NUNM) {
        int u = g_unm[b][t];
        const float4* src = (const float4*)(xf + (brow + 2*u) * DD);
        out[d] = src[d];
    } else {
        int j = t - NUNM;
        const float4* dsrc = (const float4*)(xf + (brow + 2*j + 1) * DD);
        float4 v = dsrc[d];
        int cnt = g_dcnt[b][j];
        if (cnt) {
            #pragma unroll
            for (int k = 0; k < RR; k++) {
                if (sdst[k] == j) {
                    const float4* s2 =
                        (const float4*)(xf + (brow + 2*ssrc[k]) * DD);
                    float4 a = s2[d];
                    v.x += a.x; v.y += a.y; v.z += a.z; v.w += a.w;
                }
            }
            float inv = 1.0f / (float)(1 + cnt);
            v.x *= inv; v.y *= inv; v.z *= inv; v.w *= inv;
        }
        out[d] = v;
    }
}

// ---------------------------------------------------------------------------
// kernel_launch
// ---------------------------------------------------------------------------
extern "C" void kernel_launch(void* const* d_in, const int* in_sizes, int n_in,
                              void* d_out, int out_size)
{
    const float* q_x       = (const float*)d_in[0];
    const float* ln1_w     = (const float*)d_in[1];
    const float* ln1_b     = (const float*)d_in[2];
    const float* in_proj_w = (const float*)d_in[3];
    const float* in_proj_b = (const float*)d_in[4];
    const float* out_w     = (const float*)d_in[5];
    const float* out_b     = (const float*)d_in[6];
    const float* ln2_w     = (const float*)d_in[7];
    const float* ln2_b     = (const float*)d_in[8];
    const float* fc_w      = (const float*)d_in[9];
    const float* fc_b      = (const float*)d_in[10];
    const float* proj_w    = (const float*)d_in[11];
    const float* proj_b    = (const float*)d_in[12];
    float* outp = (float*)d_out;

    float *p_h, *p_qkv, *p_o, *p_xf, *p_m, *p_nmax, *p_xm, *p_h2, *p_t4;
    float *p_wavgT, *p_bavg;
    int *p_nidx;
    cudaGetSymbolAddress((void**)&p_h,     g_h);
    cudaGetSymbolAddress((void**)&p_qkv,   g_qkv);
    cudaGetSymbolAddress((void**)&p_o,     g_o);
    cudaGetSymbolAddress((void**)&p_xf,    g_xf);
    cudaGetSymbolAddress((void**)&p_m,     g_m);
    cudaGetSymbolAddress((void**)&p_wavgT, g_wavgT);
    cudaGetSymbolAddress((void**)&p_bavg,  g_bavg);
    cudaGetSymbolAddress((void**)&p_nmax,  g_nmax);
    cudaGetSymbolAddress((void**)&p_nidx,  g_nidx);
    cudaGetSymbolAddress((void**)&p_xm,    g_xm);
    cudaGetSymbolAddress((void**)&p_h2,    g_h2);
    cudaGetSymbolAddress((void**)&p_t4,    g_t4);

    static const int ATT_SMEM = (NTOK*KST*2 + 8*PRST + 8*HDIM) * 4;
    cudaFuncSetAttribute(attn_kernel,
                         cudaFuncAttributeMaxDynamicSharedMemorySize, ATT_SMEM);

    // 0. head-averaged k weights (exact metric path)
    wavg_kernel<<<HDIM, 256>>>(in_proj_w, in_proj_b, p_wavgT, p_bavg);

    // 1. LN1
    ln_kernel<<<MROWS, 256>>>(q_x, ln1_w, ln1_b, p_h);

    // 2. qkv = h @ in_proj_w^T + b  (TF32 tensor cores)
    gemm_tf32<0><<<dim3(3072/128, (MROWS+127)/128), 256>>>(
        p_h, in_proj_w, in_proj_b, nullptr, p_qkv, MROWS, 3072, 1024);

    // 3. metric (fp32 exact) + normalize
    metricrow_kernel<<<MROWS, 256>>>(p_h, p_wavgT, p_bavg, p_m);

    // 4. attention -> o
    attn_kernel<<<BATCH*HEADS, 256, ATT_SMEM>>>(p_qkv, p_o);

    // 5. x = q_x + o @ out_w^T + out_b
    gemm_tf32<1><<<dim3(1024/128, (MROWS+127)/128), 256>>>(
        p_o, out_w, out_b, q_x, p_xf, MROWS, 1024, 1024);

    // 6. node scores
    nodescore_kernel<<<dim3(NA, BATCH), 128>>>(p_m, p_nmax, p_nidx);

    // 7. stable ranks / merge bookkeeping
    topo_kernel<<<BATCH, 160>>>(p_nmax, p_nidx);

    // 8. merge tokens 257 -> 241
    merge_kernel<<<BATCH*NOUT, 256>>>(p_xf, p_xm);

    // 9. LN2
    ln_kernel<<<MOUT, 256>>>(p_xm, ln2_w, ln2_b, p_h2);

    // 10. t = gelu(h2 @ fc_w^T + fc_b)
    gemm_tf32<2><<<dim3(4096/128, (MOUT+127)/128), 256>>>(
        p_h2, fc_w, fc_b, nullptr, p_t4, MOUT, 4096, 1024);

    // 11. out = x + t @ proj_w^T + proj_b
    gemm_tf32<1><<<dim3(1024/128, (MOUT+127)/128), 256>>>(
        p_t4, proj_w, proj_b, p_xm, outp, MOUT, 1024, 4096);
}

// round 11
// speedup vs baseline: 1.0017x; 1.0002x over previous
#include <cuda_runtime.h>
#include <math.h>

// ---------------------------------------------------------------------------
// Problem constants
// ---------------------------------------------------------------------------
#define DD    1024
#define NTOK  257
#define BATCH 32
#define HEADS 16
#define HDIM  64
#define RR    16
#define NA    129        // even tokens (a side)
#define NB    128        // odd tokens  (b side)
#define NUNM  113        // NA - RR
#define NOUT  241        // NUNM + NB
#define MROWS (BATCH*NTOK)   // 8224
#define MOUT  (BATCH*NOUT)   // 7712

// ---------------------------------------------------------------------------
// Scratch (device globals -- no allocation allowed)
// ---------------------------------------------------------------------------
__device__ float g_h   [MROWS*DD];          // LN1 output (fp32 exact)
__device__ float g_qkv [MROWS*3*DD];        // qkv projections (tf32 accuracy)
__device__ float g_o   [MROWS*DD];          // attention output
__device__ float g_xf  [MROWS*DD];          // x after attention residual
__device__ float g_m   [MROWS*HDIM];        // normalized metric (fp32 path)
__device__ float g_wavgT[DD*HDIM];          // head-averaged Wk, transposed [k][d]
__device__ float g_bavg [HDIM];
__device__ float g_nmax[BATCH*NA];
__device__ int   g_nidx[BATCH*NA];
__device__ int   g_unm [BATCH][NUNM];
__device__ int   g_src [BATCH][RR];
__device__ int   g_dst [BATCH][RR];
__device__ int   g_dcnt[BATCH][NB];
__device__ float g_xm  [MOUT*DD];           // merged x
__device__ float g_h2  [MOUT*DD];           // LN2 output
__device__ float g_t4  [MOUT*4*DD];         // fc+gelu output

// ---------------------------------------------------------------------------
// Helpers
// ---------------------------------------------------------------------------
__device__ __forceinline__ float gelu_exact(float x) {
    return 0.5f * x * (1.0f + erff(x * 0.70710678118654752440f));
}

__device__ __forceinline__ unsigned f2tf(float x) {
    unsigned u;
    asm("cvt.rna.tf32.f32 %0, %1;" : "=r"(u) : "f"(x));
    return u;
}

__device__ __forceinline__ void mma_tf32(float c[4], const unsigned a[4],
                                         const unsigned b[2]) {
    asm volatile(
        "mma.sync.aligned.m16n8k8.row.col.f32.tf32.tf32.f32 "
        "{%0,%1,%2,%3}, {%4,%5,%6,%7}, {%8,%9}, {%0,%1,%2,%3};\n"
        : "+f"(c[0]), "+f"(c[1]), "+f"(c[2]), "+f"(c[3])
        : "r"(a[0]), "r"(a[1]), "r"(a[2]), "r"(a[3]),
          "r"(b[0]), "r"(b[1]));
}

// ---------------------------------------------------------------------------
// LayerNorm: one block per row of 1024, 256 threads (4 floats/thread)
// ---------------------------------------------------------------------------
__global__ __launch_bounds__(256)
void ln_kernel(const float* __restrict__ x, const float* __restrict__ w,
               const float* __restrict__ b, float* __restrict__ y)
{
    int r = blockIdx.x;
    const float4* xr = (const float4*)(x + (size_t)r * DD);
    float4 v = xr[threadIdx.x];
    float s  = v.x + v.y + v.z + v.w;
    float s2 = v.x*v.x + v.y*v.y + v.z*v.z + v.w*v.w;
    #pragma unroll
    for (int off = 16; off; off >>= 1) {
        s  += __shfl_xor_sync(0xffffffffu, s,  off);
        s2 += __shfl_xor_sync(0xffffffffu, s2, off);
    }
    __shared__ float ws[8], ws2[8];
    int wid = threadIdx.x >> 5, lid = threadIdx.x & 31;
    if (lid == 0) { ws[wid] = s; ws2[wid] = s2; }
    __syncthreads();
    __shared__ float smu, srstd;
    if (threadIdx.x == 0) {
        float S = 0, S2 = 0;
        #pragma unroll
        for (int i = 0; i < 8; i++) { S += ws[i]; S2 += ws2[i]; }
        float mu  = S * (1.0f / DD);
        float var = S2 * (1.0f / DD) - mu * mu;
        smu = mu; srstd = rsqrtf(var + 1e-5f);
    }
    __syncthreads();
    float mu = smu, rstd = srstd;
    float4 wv = ((const float4*)w)[threadIdx.x];
    float4 bv = ((const float4*)b)[threadIdx.x];
    float4 o;
    o.x = (v.x - mu) * rstd * wv.x + bv.x;
    o.y = (v.y - mu) * rstd * wv.y + bv.y;
    o.z = (v.z - mu) * rstd * wv.z + bv.z;
    o.w = (v.w - mu) * rstd * wv.w + bv.w;
    ((float4*)(y + (size_t)r * DD))[threadIdx.x] = o;
}

// ---------------------------------------------------------------------------
// TF32 tensor-core GEMM (NT): C[m,n] = sum_k A[m,k]*W[n,k] + bias[n] (+epi)
// BM=BN=128, BK=32, 256 threads, warp tile 64x32 (warps 2x4).
// Smem layout [row][k] with stride 36 floats: conflict-free fragment reads.
// Register-staged gmem prefetch, single smem buffer.
// EPI 0: bias. EPI 1: +Cadd residual. EPI 2: gelu(acc+bias).
// Requires N%128==0, K%32==0; M guarded (rows clamped + epilogue guard).
// ---------------------------------------------------------------------------
#define SAS 36

template<int EPI>
__global__ __launch_bounds__(256, 1)
void gemm_tf32(const float* __restrict__ A, const float* __restrict__ W,
               const float* __restrict__ bias, const float* __restrict__ Cadd,
               float* __restrict__ C, int M, int N, int K)
{
    __shared__ unsigned As[128*SAS];
    __shared__ unsigned Bs[128*SAS];

    int tid = threadIdx.x;
    int bx = blockIdx.x, by = blockIdx.y;
    int rbase = tid >> 3;          // 0..31
    int c4    = tid & 7;           // 0..7  (float4 column group)

    const float* Ap[4];
    const float* Wp[4];
    #pragma unroll
    for (int i = 0; i < 4; i++) {
        int ar = by*128 + rbase + 32*i;
        if (ar >= M) ar = M - 1;                // clamp (epilogue guards)
        Ap[i] = A + (size_t)ar * K + c4*4;
        Wp[i] = W + (size_t)(bx*128 + rbase + 32*i) * K + c4*4;
    }

    float4 areg[4], breg[4];
    #pragma unroll
    for (int i = 0; i < 4; i++) {
        areg[i] = *(const float4*)(Ap[i]);
        breg[i] = *(const float4*)(Wp[i]);
    }

    float acc[4][4][4];
    #pragma unroll
    for (int mt = 0; mt < 4; mt++)
        #pragma unroll
        for (int nt = 0; nt < 4; nt++)
            #pragma unroll
            for (int q = 0; q < 4; q++) acc[mt][nt][q] = 0.0f;

    int w = tid >> 5, l = tid & 31;
    int wm = w >> 2, wn = w & 3;          // 2 x 4 warp grid
    int mrow = l >> 2;                    // 0..7
    int kc   = l & 3;                     // 0..3

    for (int kc0 = 0; kc0 < K; kc0 += 32) {
        // stage regs -> smem (with tf32 rounding)
        #pragma unroll
        for (int i = 0; i < 4; i++) {
            int so = (rbase + 32*i) * SAS + c4*4;
            As[so+0] = f2tf(areg[i].x); As[so+1] = f2tf(areg[i].y);
            As[so+2] = f2tf(areg[i].z); As[so+3] = f2tf(areg[i].w);
            Bs[so+0] = f2tf(breg[i].x); Bs[so+1] = f2tf(breg[i].y);
            Bs[so+2] = f2tf(breg[i].z); Bs[so+3] = f2tf(breg[i].w);
        }
        __syncthreads();

        bool more = (kc0 + 32) < K;
        if (more) {
            #pragma unroll
            for (int i = 0; i < 4; i++) {
                areg[i] = *(const float4*)(Ap[i] + kc0 + 32);
                breg[i] = *(const float4*)(Wp[i] + kc0 + 32);
            }
        }

        #pragma unroll
        for (int kk = 0; kk < 4; kk++) {
            unsigned af[4][4], bf[4][2];
            #pragma unroll
            for (int mt = 0; mt < 4; mt++) {
                int base = (wm*64 + mt*16 + mrow) * SAS + kk*8 + kc;
                af[mt][0] = As[base];
                af[mt][1] = As[base + 8*SAS];
                af[mt][2] = As[base + 4];
                af[mt][3] = As[base + 8*SAS + 4];
            }
            #pragma unroll
            for (int nt = 0; nt < 4; nt++) {
                int base = (wn*32 + nt*8 + mrow) * SAS + kk*8 + kc;
                bf[nt][0] = Bs[base];
                bf[nt][1] = Bs[base + 4];
            }
            #pragma unroll
            for (int mt = 0; mt < 4; mt++)
                #pragma unroll
                for (int nt = 0; nt < 4; nt++)
                    mma_tf32(acc[mt][nt], af[mt], bf[nt]);
        }
        if (more) __syncthreads();
    }

    // epilogue
    int gr0 = by*128 + wm*64;
    int gc0 = bx*128 + wn*32;
    #pragma unroll
    for (int mt = 0; mt < 4; mt++) {
        #pragma unroll
        for (int nt = 0; nt < 4; nt++) {
            int col = gc0 + nt*8 + kc*2;
            float2 bv = *(const float2*)(bias + col);
            #pragma unroll
            for (int half = 0; half < 2; half++) {
                int row = gr0 + mt*16 + mrow + half*8;
                if (row >= M) continue;
                float r0 = acc[mt][nt][half*2+0] + bv.x;
                float r1 = acc[mt][nt][half*2+1] + bv.y;
                if constexpr (EPI == 1) {
                    float2 cv = *(const float2*)(Cadd + (size_t)row*N + col);
                    r0 += cv.x; r1 += cv.y;
                }
                if constexpr (EPI == 2) {
                    r0 = gelu_exact(r0); r1 = gelu_exact(r1);
                }
                float2 ov = {r0, r1};
                *(float2*)(C + (size_t)row*N + col) = ov;
            }
        }
    }
}

// ---------------------------------------------------------------------------
// Fused attention: one block per (b,h). K,V resident in smem (stride 65),
// per-warp softmax over 257 keys.
// ---------------------------------------------------------------------------
#define KST 65
#define PRST 260
__global__ __launch_bounds__(256)
void attn_kernel(const float* __restrict__ qkv, float* __restrict__ o)
{
    extern __shared__ float sm[];
    float* Ks = sm;                       // 257*65
    float* Vs = sm + NTOK*KST;            // 257*65
    float* Pr = Vs + NTOK*KST;            // 8*260
    float* Qb = Pr + 8*PRST;              // 8*64

    int bh = blockIdx.x;
    int b = bh >> 4, hh = bh & 15;
    const float* base = qkv + (size_t)b * NTOK * (3*DD);

    for (int idx = threadIdx.x; idx < NTOK*HDIM; idx += blockDim.x) {
        int j = idx >> 6, d = idx & 63;
        Ks[j*KST + d] = base[(size_t)j*(3*DD) + DD   + hh*HDIM + d];
        Vs[j*KST + d] = base[(size_t)j*(3*DD) + 2*DD + hh*HDIM + d];
    }
    __syncthreads();

    int w = threadIdx.x >> 5, l = threadIdx.x & 31;
    float* pr = Pr + w * PRST;
    float* qb = Qb + w * HDIM;

    for (int n = w; n < NTOK; n += 8) {
        const float* qrow = base + (size_t)n*(3*DD) + hh*HDIM;
        qb[l]      = qrow[l];
        qb[l + 32] = qrow[l + 32];
        __syncwarp();
        float mx = -INFINITY;
        for (int j = l; j < NTOK; j += 32) {
            float s = 0.0f;
            #pragma unroll
            for (int d = 0; d < HDIM; d++) s += qb[d] * Ks[j*KST + d];
            s *= 0.125f;
            pr[j] = s;
            mx = fmaxf(mx, s);
        }
        #pragma unroll
        for (int off = 16; off; off >>= 1)
            mx = fmaxf(mx, __shfl_xor_sync(0xffffffffu, mx, off));
        float sum = 0.0f;
        for (int j = l; j < NTOK; j += 32) {
            float e = expf(pr[j] - mx);
            pr[j] = e;
            sum += e;
        }
        #pragma unroll
        for (int off = 16; off; off >>= 1)
            sum += __shfl_xor_sync(0xffffffffu, sum, off);
        float inv = 1.0f / sum;
        __syncwarp();
        float o0 = 0.0f, o1 = 0.0f;
        for (int j = 0; j < NTOK; j++) {
            float p = pr[j];
            o0 += p * Vs[j*KST + l];
            o1 += p * Vs[j*KST + l + 32];
        }
        float* orow = o + ((size_t)b*NTOK + n) * DD + hh*HDIM;
        orow[l]      = o0 * inv;
        orow[l + 32] = o1 * inv;
        __syncwarp();
    }
}

// ---------------------------------------------------------------------------
// Head-averaged k-weights (fp32 exact metric path):
// wavgT[c*64+d] = mean_h in_proj_w[D + h*64 + d][c]; bavg likewise.
// ---------------------------------------------------------------------------
__global__ __launch_bounds__(256)
void wavg_kernel(const float* __restrict__ Wqkv, const float* __restrict__ bqkv,
                 float* __restrict__ wavgT, float* __restrict__ bavg)
{
    int d = blockIdx.x;                   // 0..63
    for (int c = threadIdx.x; c < DD; c += 256) {
        float s = 0.0f;
        #pragma unroll
        for (int h = 0; h < HEADS; h++)
            s += Wqkv[(size_t)(DD + h*HDIM + d) * DD + c];
        wavgT[c*HDIM + d] = s * (1.0f / HEADS);
    }
    if (threadIdx.x == 0) {
        float s = 0.0f;
        #pragma unroll
        for (int h = 0; h < HEADS; h++) s += bqkv[DD + h*HDIM + d];
        bavg[d] = s * (1.0f / HEADS);
    }
}

// ---------------------------------------------------------------------------
// metric row: m[row][d] = normalize_d( dot(h_row, wavgT[:,d]) + bavg[d] )
// Block per row, 256 threads: thread (seg = tid>>6, d = tid&63).
// ---------------------------------------------------------------------------
__global__ __launch_bounds__(256)
void metricrow_kernel(const float* __restrict__ h,
                      const float* __restrict__ wavgT,
                      const float* __restrict__ bavg,
                      float* __restrict__ m)
{
    int row = blockIdx.x;
    __shared__ float hs[DD];
    ((float4*)hs)[threadIdx.x] =
        ((const float4*)(h + (size_t)row * DD))[threadIdx.x];
    __syncthreads();

    int d = threadIdx.x & 63, seg = threadIdx.x >> 6;
    const float* wp = wavgT + (size_t)seg * 256 * HDIM + d;
    const float* hp = hs + seg * 256;
    float acc = 0.0f;
    #pragma unroll 8
    for (int k = 0; k < 256; k++) acc += hp[k] * wp[k*HDIM];

    __shared__ float red[256];
    red[threadIdx.x] = acc;
    __syncthreads();

    float v = 0.0f;
    if (threadIdx.x < 64)
        v = red[d] + red[64+d] + red[128+d] + red[192+d] + bavg[d];
    float sq = v * v;
    #pragma unroll
    for (int off = 16; off; off >>= 1)
        sq += __shfl_xor_sync(0xffffffffu, sq, off);
    __shared__ float s2w[8];
    if ((threadIdx.x & 31) == 0) s2w[threadIdx.x >> 5] = sq;
    __syncthreads();
    if (threadIdx.x < 64) {
        float tot = s2w[0] + s2w[1];
        m[(size_t)row * HDIM + d] = v * rsqrtf(tot);
    }
}

// ---------------------------------------------------------------------------
// node scores: block (i,b) computes max_j dot(a_i, bm_j) and argmax (first
// max wins). Row i==0 forced to -inf.
// ---------------------------------------------------------------------------
__global__ __launch_bounds__(128)
void nodescore_kernel(const float* __restrict__ m,
                      float* __restrict__ nmax, int* __restrict__ nidx)
{
    int i = blockIdx.x, b = blockIdx.y;
    if (i == 0) {
        if (threadIdx.x == 0) { nmax[b*NA] = -INFINITY; nidx[b*NA] = 0; }
        return;
    }
    __shared__ float av[HDIM];
    if (threadIdx.x < HDIM)
        av[threadIdx.x] = m[((size_t)b*NTOK + 2*i) * HDIM + threadIdx.x];
    __syncthreads();
    int j = threadIdx.x;
    const float* bm = m + ((size_t)b*NTOK + 2*j + 1) * HDIM;
    float s = 0.0f;
    #pragma unroll
    for (int d = 0; d < HDIM; d++) s += av[d] * bm[d];
    __shared__ float sv[128];
    __shared__ int   si[128];
    sv[j] = s; si[j] = j;
    __syncthreads();
    #pragma unroll
    for (int st = 64; st; st >>= 1) {
        if (threadIdx.x < st) {
            float o = sv[threadIdx.x + st]; int oi = si[threadIdx.x + st];
            if (o > sv[threadIdx.x] ||
                (o == sv[threadIdx.x] && oi < si[threadIdx.x])) {
                sv[threadIdx.x] = o; si[threadIdx.x] = oi;
            }
        }
        __syncthreads();
    }
    if (threadIdx.x == 0) { nmax[b*NA + i] = sv[0]; nidx[b*NA + i] = si[0]; }
}

// ---------------------------------------------------------------------------
// Stable descending argsort via ranks; build unm/src/dst/dcnt per batch.
// ---------------------------------------------------------------------------
__global__ __launch_bounds__(160)
void topo_kernel(const float* __restrict__ nmax, const int* __restrict__ nidx)
{
    int b = blockIdx.x;
    __shared__ float nm[NA];
    __shared__ int   rk[NA];
    int t = threadIdx.x;
    if (t < NA) nm[t] = nmax[b*NA + t];
    __syncthreads();
    if (t < NA) {
        float mi = nm[t];
        int r = 0;
        for (int j = 0; j < NA; j++) {
            float mj = nm[j];
            r += (mj > mi) || (mj == mi && j < t);
        }
        rk[t] = r;
        if (r < RR) {
            g_src[b][r] = t;
            g_dst[b][r] = nidx[b*NA + t];
        }
    }
    __syncthreads();
    if (t == 0) {
        int pos = 0;
        for (int i = 0; i < NA; i++)
            if (rk[i] >= RR) g_unm[b][pos++] = i;
    }
    if (t < NB) {
        int c = 0;
        for (int k = 0; k < RR; k++) c += (g_dst[b][k] == t);
        g_dcnt[b][t] = c;
    }
}

// ---------------------------------------------------------------------------
// ToME merge: out token t<113 = s[unm[t]]; else d[j] + mapped src, / size.
// ---------------------------------------------------------------------------
__global__ __launch_bounds__(256)
void merge_kernel(const float* __restrict__ xf, float* __restrict__ xm)
{
    int t = blockIdx.x % NOUT;
    int b = blockIdx.x / NOUT;
    __shared__ int ssrc[RR], sdst[RR];
    if (threadIdx.x < RR) {
        ssrc[threadIdx.x] = g_src[b][threadIdx.x];
        sdst[threadIdx.x] = g_dst[b][threadIdx.x];
    }
    __syncthreads();
    size_t brow = (size_t)b * NTOK;
    float4* out = (float4*)(xm + ((size_t)b * NOUT + t) * DD);
    int d = threadIdx.x;
    if (t < NUNM) {
        int u = g_unm[b][t];
        const float4* src = (const float4*)(xf + (brow + 2*u) * DD);
        out[d] = src[d];
    } else {
        int j = t - NUNM;
        const float4* dsrc = (const float4*)(xf + (brow + 2*j + 1) * DD);
        float4 v = dsrc[d];
        int cnt = g_dcnt[b][j];
        if (cnt) {
            #pragma unroll
            for (int k = 0; k < RR; k++) {
                if (sdst[k] == j) {
                    const float4* s2 =
                        (const float4*)(xf + (brow + 2*ssrc[k]) * DD);
                    float4 a = s2[d];
                    v.x += a.x; v.y += a.y; v.z += a.z; v.w += a.w;
                }
            }
            float inv = 1.0f / (float)(1 + cnt);
            v.x *= inv; v.y *= inv; v.z *= inv; v.w *= inv;
        }
        out[d] = v;
    }
}

// ---------------------------------------------------------------------------
// kernel_launch
// ---------------------------------------------------------------------------
extern "C" void kernel_launch(void* const* d_in, const int* in_sizes, int n_in,
                              void* d_out, int out_size)
{
    const float* q_x       = (const float*)d_in[0];
    const float* ln1_w     = (const float*)d_in[1];
    const float* ln1_b     = (const float*)d_in[2];
    const float* in_proj_w = (const float*)d_in[3];
    const float* in_proj_b = (const float*)d_in[4];
    const float* out_w     = (const float*)d_in[5];
    const float* out_b     = (const float*)d_in[6];
    const float* ln2_w     = (const float*)d_in[7];
    const float* ln2_b     = (const float*)d_in[8];
    const float* fc_w      = (const float*)d_in[9];
    const float* fc_b      = (const float*)d_in[10];
    const float* proj_w    = (const float*)d_in[11];
    const float* proj_b    = (const float*)d_in[12];
    float* outp = (float*)d_out;

    float *p_h, *p_qkv, *p_o, *p_xf, *p_m, *p_nmax, *p_xm, *p_h2, *p_t4;
    float *p_wavgT, *p_bavg;
    int *p_nidx;
    cudaGetSymbolAddress((void**)&p_h,     g_h);
    cudaGetSymbolAddress((void**)&p_qkv,   g_qkv);
    cudaGetSymbolAddress((void**)&p_o,     g_o);
    cudaGetSymbolAddress((void**)&p_xf,    g_xf);
    cudaGetSymbolAddress((void**)&p_m,     g_m);
    cudaGetSymbolAddress((void**)&p_wavgT, g_wavgT);
    cudaGetSymbolAddress((void**)&p_bavg,  g_bavg);
    cudaGetSymbolAddress((void**)&p_nmax,  g_nmax);
    cudaGetSymbolAddress((void**)&p_nidx,  g_nidx);
    cudaGetSymbolAddress((void**)&p_xm,    g_xm);
    cudaGetSymbolAddress((void**)&p_h2,    g_h2);
    cudaGetSymbolAddress((void**)&p_t4,    g_t4);

    static const int ATT_SMEM = (NTOK*KST*2 + 8*PRST + 8*HDIM) * 4;
    cudaFuncSetAttribute(attn_kernel,
                         cudaFuncAttributeMaxDynamicSharedMemorySize, ATT_SMEM);

    // 0. head-averaged k weights (exact metric path)
    wavg_kernel<<<HDIM, 256>>>(in_proj_w, in_proj_b, p_wavgT, p_bavg);

    // 1. LN1
    ln_kernel<<<MROWS, 256>>>(q_x, ln1_w, ln1_b, p_h);

    // 2. qkv = h @ in_proj_w^T + b  (TF32 tensor cores)
    gemm_tf32<0><<<dim3(3072/128, (MROWS+127)/128), 256>>>(
        p_h, in_proj_w, in_proj_b, nullptr, p_qkv, MROWS, 3072, 1024);

    // 3. metric (fp32 exact) + normalize
    metricrow_kernel<<<MROWS, 256>>>(p_h, p_wavgT, p_bavg, p_m);

    // 4. attention -> o
    attn_kernel<<<BATCH*HEADS, 256, ATT_SMEM>>>(p_qkv, p_o);

    // 5. x = q_x + o @ out_w^T + out_b
    gemm_tf32<1><<<dim3(1024/128, (MROWS+127)/128), 256>>>(
        p_o, out_w, out_b, q_x, p_xf, MROWS, 1024, 1024);

    // 6. node scores
    nodescore_kernel<<<dim3(NA, BATCH), 128>>>(p_m, p_nmax, p_nidx);

    // 7. stable ranks / merge bookkeeping
    topo_kernel<<<BATCH, 160>>>(p_nmax, p_nidx);

    // 8. merge tokens 257 -> 241
    merge_kernel<<<BATCH*NOUT, 256>>>(p_xf, p_xm);

    // 9. LN2
    ln_kernel<<<MOUT, 256>>>(p_xm, ln2_w, ln2_b, p_h2);

    // 10. t = gelu(h2 @ fc_w^T + fc_b)
    gemm_tf32<2><<<dim3(4096/128, (MOUT+127)/128), 256>>>(
        p_h2, fc_w, fc_b, nullptr, p_t4, MOUT, 4096, 1024);

    // 11. out = x + t @ proj_w^T + proj_b
    gemm_tf32<1><<<dim3(1024/128, (MOUT+127)/128), 256>>>(
        p_t4, proj_w, proj_b, p_xm, outp, MOUT, 1024, 4096);
}

// round 14
// speedup vs baseline: 1.1010x; 1.0992x over previous
#include <cuda_runtime.h>
#include <math.h>
#include <stdint.h>

// ---------------------------------------------------------------------------
// Problem constants
// ---------------------------------------------------------------------------
#define DD    1024
#define NTOK  257
#define BATCH 32
#define HEADS 16
#define HDIM  64
#define RR    16
#define NA    129        // even tokens (a side)
#define NB    128        // odd tokens  (b side)
#define NUNM  113        // NA - RR
#define NOUT  241        // NUNM + NB
#define MROWS (BATCH*NTOK)   // 8224
#define MOUT  (BATCH*NOUT)   // 7712

// ---------------------------------------------------------------------------
// Scratch (device globals -- no allocation allowed)
// ---------------------------------------------------------------------------
__device__ float g_h   [MROWS*DD];          // LN1 output (fp32 exact, metric path)
__device__ float g_ht  [MROWS*DD];          // LN1 output (tf32-rounded, GEMM A)
__device__ float g_qkv [MROWS*3*DD];        // qkv projections
__device__ float g_o   [MROWS*DD];          // attention output (tf32-rounded)
__device__ float g_xf  [MROWS*DD];          // x after attention residual (exact)
__device__ float g_m   [MROWS*HDIM];        // normalized metric (fp32 path)
__device__ float g_wavgT[DD*HDIM];          // head-averaged Wk, transposed
__device__ float g_bavg [HDIM];
__device__ float g_nmax[BATCH*NA];
__device__ int   g_nidx[BATCH*NA];
__device__ int   g_unm [BATCH][NUNM];
__device__ int   g_src [BATCH][RR];
__device__ int   g_dst [BATCH][RR];
__device__ int   g_dcnt[BATCH][NB];
__device__ float g_xm  [MOUT*DD];           // merged x (exact)
__device__ float g_h2  [MOUT*DD];           // LN2 output (tf32-rounded)
__device__ float g_t4  [MOUT*4*DD];         // fc+gelu output (tf32-rounded)
// tf32-rounded weight copies
__device__ float g_w_in  [3*DD*DD];
__device__ float g_w_out [DD*DD];
__device__ float g_w_fc  [4*DD*DD];
__device__ float g_w_proj[4*DD*DD];

// ---------------------------------------------------------------------------
// Helpers
// ---------------------------------------------------------------------------
__device__ __forceinline__ float gelu_exact(float x) {
    return 0.5f * x * (1.0f + erff(x * 0.70710678118654752440f));
}

__device__ __forceinline__ unsigned f2tf(float x) {
    unsigned u;
    asm("cvt.rna.tf32.f32 %0, %1;" : "=r"(u) : "f"(x));
    return u;
}
__device__ __forceinline__ float rtf(float x) {
    return __uint_as_float(f2tf(x));
}

__device__ __forceinline__ uint32_t smem_u32(const void* p) {
    uint32_t a;
    asm("{ .reg .u64 t; cvta.to.shared.u64 t, %1; cvt.u32.u64 %0, t; }"
        : "=r"(a) : "l"(p));
    return a;
}

__device__ __forceinline__ void cp16(uint32_t s, const void* g) {
    asm volatile("cp.async.cg.shared.global [%0], [%1], 16;"
                 :: "r"(s), "l"(g) : "memory");
}
#define CP_COMMIT() asm volatile("cp.async.commit_group;" ::: "memory")
#define CP_WAIT1()  asm volatile("cp.async.wait_group 1;" ::: "memory")
#define CP_WAIT0()  asm volatile("cp.async.wait_group 0;" ::: "memory")

__device__ __forceinline__ void mma_tf32(float c[4], const unsigned a[4],
                                         const unsigned b[2]) {
    asm volatile(
        "mma.sync.aligned.m16n8k8.row.col.f32.tf32.tf32.f32 "
        "{%0,%1,%2,%3}, {%4,%5,%6,%7}, {%8,%9}, {%0,%1,%2,%3};\n"
        : "+f"(c[0]), "+f"(c[1]), "+f"(c[2]), "+f"(c[3])
        : "r"(a[0]), "r"(a[1]), "r"(a[2]), "r"(a[3]),
          "r"(b[0]), "r"(b[1]));
}

// ---------------------------------------------------------------------------
// Round weights to tf32 (rna) into scratch copies
// ---------------------------------------------------------------------------
__global__ __launch_bounds__(256)
void roundw_kernel(const float4* __restrict__ s, float4* __restrict__ d, int n4)
{
    int i = blockIdx.x * blockDim.x + threadIdx.x;
    if (i < n4) {
        float4 v = s[i];
        v.x = rtf(v.x); v.y = rtf(v.y); v.z = rtf(v.z); v.w = rtf(v.w);
        d[i] = v;
    }
}

// ---------------------------------------------------------------------------
// LayerNorm: one block per row of 1024, 256 threads (4 floats/thread).
// y: exact output (nullable). yt: tf32-rounded output (nullable).
// ---------------------------------------------------------------------------
__global__ __launch_bounds__(256)
void ln_kernel(const float* __restrict__ x, const float* __restrict__ w,
               const float* __restrict__ b, float* __restrict__ y,
               float* __restrict__ yt)
{
    int r = blockIdx.x;
    const float4* xr = (const float4*)(x + (size_t)r * DD);
    float4 v = xr[threadIdx.x];
    float s  = v.x + v.y + v.z + v.w;
    float s2 = v.x*v.x + v.y*v.y + v.z*v.z + v.w*v.w;
    #pragma unroll
    for (int off = 16; off; off >>= 1) {
        s  += __shfl_xor_sync(0xffffffffu, s,  off);
        s2 += __shfl_xor_sync(0xffffffffu, s2, off);
    }
    __shared__ float ws[8], ws2[8];
    int wid = threadIdx.x >> 5, lid = threadIdx.x & 31;
    if (lid == 0) { ws[wid] = s; ws2[wid] = s2; }
    __syncthreads();
    __shared__ float smu, srstd;
    if (threadIdx.x == 0) {
        float S = 0, S2 = 0;
        #pragma unroll
        for (int i = 0; i < 8; i++) { S += ws[i]; S2 += ws2[i]; }
        float mu  = S * (1.0f / DD);
        float var = S2 * (1.0f / DD) - mu * mu;
        smu = mu; srstd = rsqrtf(var + 1e-5f);
    }
    __syncthreads();
    float mu = smu, rstd = srstd;
    float4 wv = ((const float4*)w)[threadIdx.x];
    float4 bv = ((const float4*)b)[threadIdx.x];
    float4 o;
    o.x = (v.x - mu) * rstd * wv.x + bv.x;
    o.y = (v.y - mu) * rstd * wv.y + bv.y;
    o.z = (v.z - mu) * rstd * wv.z + bv.z;
    o.w = (v.w - mu) * rstd * wv.w + bv.w;
    if (y)
        ((float4*)(y + (size_t)r * DD))[threadIdx.x] = o;
    if (yt) {
        float4 t;
        t.x = rtf(o.x); t.y = rtf(o.y); t.z = rtf(o.z); t.w = rtf(o.w);
        ((float4*)(yt + (size_t)r * DD))[threadIdx.x] = t;
    }
}

// ---------------------------------------------------------------------------
// TF32 tensor-core GEMM (NT): C[m,n] = sum_k A[m,k]*W[n,k] + bias[n] (+epi)
// A and W must be tf32-pre-rounded. BM=BN=128, BK=32, 256 threads,
// warps 2x4 (warp tile 64x32). 2-stage cp.async pipeline, 2 CTAs/SM.
// Smem per buffer: A 128x36 + B 128x36 floats (stride 36 = conflict-free).
// EPI 0: bias. EPI 1: +Cadd residual. EPI 2: gelu(acc+bias), tf32-rounded out.
// Requires N % 128 == 0, K % 64 == 0; M guarded.
// ---------------------------------------------------------------------------
#define SAS 36
#define BUFF 4608                 // floats per matrix per buffer (128*36)
#define BUFSTR 9216               // floats per buffer (A+B)
#define GEMM_SMEM (2*BUFSTR*4)    // 73728 bytes

template<int EPI>
__global__ __launch_bounds__(256, 2)
void gemm_tf32(const float* __restrict__ A, const float* __restrict__ W,
               const float* __restrict__ bias, const float* __restrict__ Cadd,
               float* __restrict__ C, int M, int N, int K)
{
    extern __shared__ float smem[];
    uint32_t sbase = smem_u32(smem);

    int tid = threadIdx.x;
    int bx = blockIdx.x, by = blockIdx.y;

    // gmem -> smem mapping: thread covers (row = rbase+32i, 16B chunk c4)
    int rbase = tid >> 3;          // 0..31
    int c4    = tid & 7;           // 0..7
    const float* Ag[4];
    const float* Wg[4];
    uint32_t sA[4], sB[4];
    #pragma unroll
    for (int i = 0; i < 4; i++) {
        int row = rbase + 32*i;
        int ar = by*128 + row; if (ar >= M) ar = M - 1;   // clamp, epi guards
        Ag[i] = A + (size_t)ar * K + c4*4;
        Wg[i] = W + (size_t)(bx*128 + row) * K + c4*4;
        sA[i] = sbase + (row*SAS + c4*4) * 4;
        sB[i] = sbase + ((BUFF + row*SAS) + c4*4) * 4;
    }

    int NC = K >> 5;

    // issue stage c into buffer c&1
    auto issue = [&](int c) {
        uint32_t off = (c & 1) ? (BUFSTR*4) : 0u;
        int ko = c * 32;
        #pragma unroll
        for (int i = 0; i < 4; i++) cp16(sA[i] + off, Ag[i] + ko);
        #pragma unroll
        for (int i = 0; i < 4; i++) cp16(sB[i] + off, Wg[i] + ko);
        CP_COMMIT();
    };

    issue(0);
    issue(1);

    float acc[4][4][4];
    #pragma unroll
    for (int mt = 0; mt < 4; mt++)
        #pragma unroll
        for (int nt = 0; nt < 4; nt++)
            #pragma unroll
            for (int q = 0; q < 4; q++) acc[mt][nt][q] = 0.0f;

    int w = tid >> 5, l = tid & 31;
    int wm = w >> 2, wn = w & 3;          // 2 x 4 warp grid
    int mrow = l >> 2;                    // 0..7
    int kc   = l & 3;                     // 0..3

    for (int c = 0; c < NC; c++) {
        if (c + 1 < NC) CP_WAIT1(); else CP_WAIT0();
        __syncthreads();

        const unsigned* As = (const unsigned*)smem + (c & 1)*BUFSTR;
        const unsigned* Bs = As + BUFF;

        #pragma unroll
        for (int kk = 0; kk < 4; kk++) {
            unsigned af[4][4], bf[4][2];
            #pragma unroll
            for (int mt = 0; mt < 4; mt++) {
                int base = (wm*64 + mt*16 + mrow) * SAS + kk*8 + kc;
                af[mt][0] = As[base];
                af[mt][1] = As[base + 8*SAS];
                af[mt][2] = As[base + 4];
                af[mt][3] = As[base + 8*SAS + 4];
            }
            #pragma unroll
            for (int nt = 0; nt < 4; nt++) {
                int base = (wn*32 + nt*8 + mrow) * SAS + kk*8 + kc;
                bf[nt][0] = Bs[base];
                bf[nt][1] = Bs[base + 4];
            }
            #pragma unroll
            for (int mt = 0; mt < 4; mt++)
                #pragma unroll
                for (int nt = 0; nt < 4; nt++)
                    mma_tf32(acc[mt][nt], af[mt], bf[nt]);
        }
        __syncthreads();
        if (c + 2 < NC) issue(c + 2);
    }

    // epilogue
    int gr0 = by*128 + wm*64;
    int gc0 = bx*128 + wn*32;
    #pragma unroll
    for (int mt = 0; mt < 4; mt++) {
        #pragma unroll
        for (int nt = 0; nt < 4; nt++) {
            int col = gc0 + nt*8 + kc*2;
            float2 bv = *(const float2*)(bias + col);
            #pragma unroll
            for (int half = 0; half < 2; half++) {
                int row = gr0 + mt*16 + mrow + half*8;
                if (row >= M) continue;
                float r0 = acc[mt][nt][half*2+0] + bv.x;
                float r1 = acc[mt][nt][half*2+1] + bv.y;
                if constexpr (EPI == 1) {
                    float2 cv = *(const float2*)(Cadd + (size_t)row*N + col);
                    r0 += cv.x; r1 += cv.y;
                }
                if constexpr (EPI == 2) {
                    r0 = rtf(gelu_exact(r0)); r1 = rtf(gelu_exact(r1));
                }
                float2 ov = {r0, r1};
                *(float2*)(C + (size_t)row*N + col) = ov;
            }
        }
    }
}

// ---------------------------------------------------------------------------
// Fused attention: one block per (b,h). K,V resident in smem (stride 65),
// per-warp softmax over 257 keys. Output tf32-rounded (feeds GEMM only).
// ---------------------------------------------------------------------------
#define KST 65
#define PRST 260
__global__ __launch_bounds__(256)
void attn_kernel(const float* __restrict__ qkv, float* __restrict__ o)
{
    extern __shared__ float sm[];
    float* Ks = sm;                       // 257*65
    float* Vs = sm + NTOK*KST;            // 257*65
    float* Pr = Vs + NTOK*KST;            // 8*260
    float* Qb = Pr + 8*PRST;              // 8*64

    int bh = blockIdx.x;
    int b = bh >> 4, hh = bh & 15;
    const float* base = qkv + (size_t)b * NTOK * (3*DD);

    for (int idx = threadIdx.x; idx < NTOK*HDIM; idx += blockDim.x) {
        int j = idx >> 6, d = idx & 63;
        Ks[j*KST + d] = base[(size_t)j*(3*DD) + DD   + hh*HDIM + d];
        Vs[j*KST + d] = base[(size_t)j*(3*DD) + 2*DD + hh*HDIM + d];
    }
    __syncthreads();

    int w = threadIdx.x >> 5, l = threadIdx.x & 31;
    float* pr = Pr + w * PRST;
    float* qb = Qb + w * HDIM;

    for (int n = w; n < NTOK; n += 8) {
        const float* qrow = base + (size_t)n*(3*DD) + hh*HDIM;
        qb[l]      = qrow[l];
        qb[l + 32] = qrow[l + 32];
        __syncwarp();
        float mx = -INFINITY;
        for (int j = l; j < NTOK; j += 32) {
            float s = 0.0f;
            #pragma unroll
            for (int d = 0; d < HDIM; d++) s += qb[d] * Ks[j*KST + d];
            s *= 0.125f;
            pr[j] = s;
            mx = fmaxf(mx, s);
        }
        #pragma unroll
        for (int off = 16; off; off >>= 1)
            mx = fmaxf(mx, __shfl_xor_sync(0xffffffffu, mx, off));
        float sum = 0.0f;
        for (int j = l; j < NTOK; j += 32) {
            float e = expf(pr[j] - mx);
            pr[j] = e;
            sum += e;
        }
        #pragma unroll
        for (int off = 16; off; off >>= 1)
            sum += __shfl_xor_sync(0xffffffffu, sum, off);
        float inv = 1.0f / sum;
        __syncwarp();
        float o0 = 0.0f, o1 = 0.0f;
        for (int j = 0; j < NTOK; j++) {
            float p = pr[j];
            o0 += p * Vs[j*KST + l];
            o1 += p * Vs[j*KST + l + 32];
        }
        float* orow = o + ((size_t)b*NTOK + n) * DD + hh*HDIM;
        orow[l]      = rtf(o0 * inv);
        orow[l + 32] = rtf(o1 * inv);
        __syncwarp();
    }
}

// ---------------------------------------------------------------------------
// Head-averaged k-weights (fp32 exact metric path)
// ---------------------------------------------------------------------------
__global__ __launch_bounds__(256)
void wavg_kernel(const float* __restrict__ Wqkv, const float* __restrict__ bqkv,
                 float* __restrict__ wavgT, float* __restrict__ bavg)
{
    int d = blockIdx.x;                   // 0..63
    for (int c = threadIdx.x; c < DD; c += 256) {
        float s = 0.0f;
        #pragma unroll
        for (int h = 0; h < HEADS; h++)
            s += Wqkv[(size_t)(DD + h*HDIM + d) * DD + c];
        wavgT[c*HDIM + d] = s * (1.0f / HEADS);
    }
    if (threadIdx.x == 0) {
        float s = 0.0f;
        #pragma unroll
        for (int h = 0; h < HEADS; h++) s += bqkv[DD + h*HDIM + d];
        bavg[d] = s * (1.0f / HEADS);
    }
}

// ---------------------------------------------------------------------------
// metric row: m[row][d] = normalize_d( dot(h_row, wavgT[:,d]) + bavg[d] )
// ---------------------------------------------------------------------------
__global__ __launch_bounds__(256)
void metricrow_kernel(const float* __restrict__ h,
                      const float* __restrict__ wavgT,
                      const float* __restrict__ bavg,
                      float* __restrict__ m)
{
    int row = blockIdx.x;
    __shared__ float hs[DD];
    ((float4*)hs)[threadIdx.x] =
        ((const float4*)(h + (size_t)row * DD))[threadIdx.x];
    __syncthreads();

    int d = threadIdx.x & 63, seg = threadIdx.x >> 6;
    const float* wp = wavgT + (size_t)seg * 256 * HDIM + d;
    const float* hp = hs + seg * 256;
    float acc = 0.0f;
    #pragma unroll 8
    for (int k = 0; k < 256; k++) acc += hp[k] * wp[k*HDIM];

    __shared__ float red[256];
    red[threadIdx.x] = acc;
    __syncthreads();

    float v = 0.0f;
    if (threadIdx.x < 64)
        v = red[d] + red[64+d] + red[128+d] + red[192+d] + bavg[d];
    float sq = v * v;
    #pragma unroll
    for (int off = 16; off; off >>= 1)
        sq += __shfl_xor_sync(0xffffffffu, sq, off);
    __shared__ float s2w[8];
    if ((threadIdx.x & 31) == 0) s2w[threadIdx.x >> 5] = sq;
    __syncthreads();
    if (threadIdx.x < 64) {
        float tot = s2w[0] + s2w[1];
        m[(size_t)row * HDIM + d] = v * rsqrtf(tot);
    }
}

// ---------------------------------------------------------------------------
// node scores: block (i,b) computes max_j dot(a_i, bm_j) and argmax (first
// max wins). Row i==0 forced to -inf.
// ---------------------------------------------------------------------------
__global__ __launch_bounds__(128)
void nodescore_kernel(const float* __restrict__ m,
                      float* __restrict__ nmax, int* __restrict__ nidx)
{
    int i = blockIdx.x, b = blockIdx.y;
    if (i == 0) {
        if (threadIdx.x == 0) { nmax[b*NA] = -INFINITY; nidx[b*NA] = 0; }
        return;
    }
    __shared__ float av[HDIM];
    if (threadIdx.x < HDIM)
        av[threadIdx.x] = m[((size_t)b*NTOK + 2*i) * HDIM + threadIdx.x];
    __syncthreads();
    int j = threadIdx.x;
    const float* bm = m + ((size_t)b*NTOK + 2*j + 1) * HDIM;
    float s = 0.0f;
    #pragma unroll
    for (int d = 0; d < HDIM; d++) s += av[d] * bm[d];
    __shared__ float sv[128];
    __shared__ int   si[128];
    sv[j] = s; si[j] = j;
    __syncthreads();
    #pragma unroll
    for (int st = 64; st; st >>= 1) {
        if (threadIdx.x < st) {
            float o = sv[threadIdx.x + st]; int oi = si[threadIdx.x + st];
            if (o > sv[threadIdx.x] ||
                (o == sv[threadIdx.x] && oi < si[threadIdx.x])) {
                sv[threadIdx.x] = o; si[threadIdx.x] = oi;
            }
        }
        __syncthreads();
    }
    if (threadIdx.x == 0) { nmax[b*NA + i] = sv[0]; nidx[b*NA + i] = si[0]; }
}

// ---------------------------------------------------------------------------
// Stable descending argsort via ranks; build unm/src/dst/dcnt per batch.
// ---------------------------------------------------------------------------
__global__ __launch_bounds__(160)
void topo_kernel(const float* __restrict__ nmax, const int* __restrict__ nidx)
{
    int b = blockIdx.x;
    __shared__ float nm[NA];
    __shared__ int   rk[NA];
    int t = threadIdx.x;
    if (t < NA) nm[t] = nmax[b*NA + t];
    __syncthreads();
    if (t < NA) {
        float mi = nm[t];
        int r = 0;
        for (int j = 0; j < NA; j++) {
            float mj = nm[j];
            r += (mj > mi) || (mj == mi && j < t);
        }
        rk[t] = r;
        if (r < RR) {
            g_src[b][r] = t;
            g_dst[b][r] = nidx[b*NA + t];
        }
    }
    __syncthreads();
    if (t == 0) {
        int pos = 0;
        for (int i = 0; i < NA; i++)
            if (rk[i] >= RR) g_unm[b][pos++] = i;
    }
    if (t < NB) {
        int c = 0;
        for (int k = 0; k < RR; k++) c += (g_dst[b][k] == t);
        g_dcnt[b][t] = c;
    }
}

// ---------------------------------------------------------------------------
// ToME merge: out token t<113 = s[unm[t]]; else d[j] + mapped src, / size.
// ---------------------------------------------------------------------------
__global__ __launch_bounds__(256)
void merge_kernel(const float* __restrict__ xf, float* __restrict__ xm)
{
    int t = blockIdx.x % NOUT;
    int b = blockIdx.x / NOUT;
    __shared__ int ssrc[RR], sdst[RR];
    if (threadIdx.x < RR) {
        ssrc[threadIdx.x] = g_src[b][threadIdx.x];
        sdst[threadIdx.x] = g_dst[b][threadIdx.x];
    }
    __syncthreads();
    size_t brow = (size_t)b * NTOK;
    float4* out = (float4*)(xm + ((size_t)b * NOUT + t) * DD);
    int d = threadIdx.x;
    if (t < NUNM) {
        int u = g_unm[b][t];
        const float4* src = (const float4*)(xf + (brow + 2*u) * DD);
        out[d] = src[d];
    } else {
        int j = t - NUNM;
        const float4* dsrc = (const float4*)(xf + (brow + 2*j + 1) * DD);
        float4 v = dsrc[d];
        int cnt = g_dcnt[b][j];
        if (cnt) {
            #pragma unroll
            for (int k = 0; k < RR; k++) {
                if (sdst[k] == j) {
                    const float4* s2 =
                        (const float4*)(xf + (brow + 2*ssrc[k]) * DD);
                    float4 a = s2[d];
                    v.x += a.x; v.y += a.y; v.z += a.z; v.w += a.w;
                }
            }
            float inv = 1.0f / (float)(1 + cnt);
            v.x *= inv; v.y *= inv; v.z *= inv; v.w *= inv;
        }
        out[d] = v;
    }
}

// ---------------------------------------------------------------------------
// kernel_launch
// ---------------------------------------------------------------------------
extern "C" void kernel_launch(void* const* d_in, const int* in_sizes, int n_in,
                              void* d_out, int out_size)
{
    const float* q_x       = (const float*)d_in[0];
    const float* ln1_w     = (const float*)d_in[1];
    const float* ln1_b     = (const float*)d_in[2];
    const float* in_proj_w = (const float*)d_in[3];
    const float* in_proj_b = (const float*)d_in[4];
    const float* out_w     = (const float*)d_in[5];
    const float* out_b     = (const float*)d_in[6];
    const float* ln2_w     = (const float*)d_in[7];
    const float* ln2_b     = (const float*)d_in[8];
    const float* fc_w      = (const float*)d_in[9];
    const float* fc_b      = (const float*)d_in[10];
    const float* proj_w    = (const float*)d_in[11];
    const float* proj_b    = (const float*)d_in[12];
    float* outp = (float*)d_out;

    float *p_h, *p_ht, *p_qkv, *p_o, *p_xf, *p_m, *p_nmax, *p_xm, *p_h2, *p_t4;
    float *p_wavgT, *p_bavg, *p_win, *p_wout, *p_wfc, *p_wproj;
    int *p_nidx;
    cudaGetSymbolAddress((void**)&p_h,     g_h);
    cudaGetSymbolAddress((void**)&p_ht,    g_ht);
    cudaGetSymbolAddress((void**)&p_qkv,   g_qkv);
    cudaGetSymbolAddress((void**)&p_o,     g_o);
    cudaGetSymbolAddress((void**)&p_xf,    g_xf);
    cudaGetSymbolAddress((void**)&p_m,     g_m);
    cudaGetSymbolAddress((void**)&p_wavgT, g_wavgT);
    cudaGetSymbolAddress((void**)&p_bavg,  g_bavg);
    cudaGetSymbolAddress((void**)&p_nmax,  g_nmax);
    cudaGetSymbolAddress((void**)&p_nidx,  g_nidx);
    cudaGetSymbolAddress((void**)&p_xm,    g_xm);
    cudaGetSymbolAddress((void**)&p_h2,    g_h2);
    cudaGetSymbolAddress((void**)&p_t4,    g_t4);
    cudaGetSymbolAddress((void**)&p_win,   g_w_in);
    cudaGetSymbolAddress((void**)&p_wout,  g_w_out);
    cudaGetSymbolAddress((void**)&p_wfc,   g_w_fc);
    cudaGetSymbolAddress((void**)&p_wproj, g_w_proj);

    static const int ATT_SMEM = (NTOK*KST*2 + 8*PRST + 8*HDIM) * 4;
    cudaFuncSetAttribute(attn_kernel,
                         cudaFuncAttributeMaxDynamicSharedMemorySize, ATT_SMEM);
    cudaFuncSetAttribute(gemm_tf32<0>,
                         cudaFuncAttributeMaxDynamicSharedMemorySize, GEMM_SMEM);
    cudaFuncSetAttribute(gemm_tf32<1>,
                         cudaFuncAttributeMaxDynamicSharedMemorySize, GEMM_SMEM);
    cudaFuncSetAttribute(gemm_tf32<2>,
                         cudaFuncAttributeMaxDynamicSharedMemorySize, GEMM_SMEM);

    // 0a. round weights to tf32 copies
    roundw_kernel<<<(3*DD*DD/4 + 255)/256, 256>>>(
        (const float4*)in_proj_w, (float4*)p_win, 3*DD*DD/4);
    roundw_kernel<<<(DD*DD/4 + 255)/256, 256>>>(
        (const float4*)out_w, (float4*)p_wout, DD*DD/4);
    roundw_kernel<<<(4*DD*DD/4 + 255)/256, 256>>>(
        (const float4*)fc_w, (float4*)p_wfc, 4*DD*DD/4);
    roundw_kernel<<<(4*DD*DD/4 + 255)/256, 256>>>(
        (const float4*)proj_w, (float4*)p_wproj, 4*DD*DD/4);

    // 0b. head-averaged k weights (exact metric path)
    wavg_kernel<<<HDIM, 256>>>(in_proj_w, in_proj_b, p_wavgT, p_bavg);

    // 1. LN1 -> exact (metric) + rounded (GEMM A)
    ln_kernel<<<MROWS, 256>>>(q_x, ln1_w, ln1_b, p_h, p_ht);

    // 2. qkv = h @ in_proj_w^T + b
    gemm_tf32<0><<<dim3(3072/128, (MROWS+127)/128), 256, GEMM_SMEM>>>(
        p_ht, p_win, in_proj_b, nullptr, p_qkv, MROWS, 3072, 1024);

    // 3. metric (fp32 exact) + normalize
    metricrow_kernel<<<MROWS, 256>>>(p_h, p_wavgT, p_bavg, p_m);

    // 4. attention -> o (rounded)
    attn_kernel<<<BATCH*HEADS, 256, ATT_SMEM>>>(p_qkv, p_o);

    // 5. x = q_x + o @ out_w^T + out_b   (exact residual out)
    gemm_tf32<1><<<dim3(1024/128, (MROWS+127)/128), 256, GEMM_SMEM>>>(
        p_o, p_wout, out_b, q_x, p_xf, MROWS, 1024, 1024);

    // 6. node scores
    nodescore_kernel<<<dim3(NA, BATCH), 128>>>(p_m, p_nmax, p_nidx);

    // 7. stable ranks / merge bookkeeping
    topo_kernel<<<BATCH, 160>>>(p_nmax, p_nidx);

    // 8. merge tokens 257 -> 241
    merge_kernel<<<BATCH*NOUT, 256>>>(p_xf, p_xm);

    // 9. LN2 -> rounded only (feeds fc GEMM only)
    ln_kernel<<<MOUT, 256>>>(p_xm, ln2_w, ln2_b, nullptr, p_h2);

    // 10. t = gelu(h2 @ fc_w^T + fc_b)  (rounded out)
    gemm_tf32<2><<<dim3(4096/128, (MOUT+127)/128), 256, GEMM_SMEM>>>(
        p_h2, p_wfc, fc_b, nullptr, p_t4, MOUT, 4096, 1024);

    // 11. out = x + t @ proj_w^T + proj_b  (exact)
    gemm_tf32<1><<<dim3(1024/128, (MOUT+127)/128), 256, GEMM_SMEM>>>(
        p_t4, p_wproj, proj_b, p_xm, outp, MOUT, 1024, 4096);
}